// round 1
// baseline (speedup 1.0000x reference)
#include <cuda_runtime.h>
#include <math.h>

// ---------------- problem dims ----------------
#define BB  512
#define TT  100
#define XX  38
#define ZZ  3
#define HH  500
#define LL  20
#define G3  (3*HH)      // 1500
#define BT  (BB*TT)     // 51200

// ---------------- scratch (__device__ globals; no allocation allowed) ----------------
__device__ float g_gi[(size_t)BT * G3];    // encoder input-gates  [B,T,3H]  (~307MB)
__device__ float g_seq1[(size_t)BT * HH];  // seq buffer A         [B,T,H]
__device__ float g_seq2[(size_t)BT * HH];  // seq buffer B         [B,T,H]
__device__ float g_gh[(size_t)BB * G3];    // per-step hidden gates [B,3H]
__device__ float g_hprev[(size_t)BB * HH]; // GRU hidden state      [B,H]

// ---------------- helpers ----------------
__device__ __forceinline__ float sigm_(float x) { return 1.f / (1.f + expf(-x)); }
__device__ __forceinline__ float softplus_(float x) { return x > 15.f ? x : log1pf(expf(x)); }

// ---------------- generic tiled GEMM: C[M,N] = act(A[M,K] * B[N,K]^T + bias[N]) ----------------
// ACT: 0 none, 1 leaky_relu(0.1), 2 softplus(x)+1e-4
#define TK 16
template <int ACT>
__global__ void gemm_abt(const float* __restrict__ A, const float* __restrict__ Bm,
                         const float* __restrict__ bias, float* __restrict__ C,
                         int M, int N, int K) {
    __shared__ float As[TK][64];
    __shared__ float Bs[TK][64];
    const int bn = blockIdx.x * 64;
    const int bm = blockIdx.y * 64;
    const int tid = threadIdx.x;            // 256 threads
    const int tm = tid >> 4, tn = tid & 15; // 16x16 thread grid, 4x4 micro-tile

    float acc[4][4] = {};
    for (int k0 = 0; k0 < K; k0 += TK) {
        #pragma unroll
        for (int i = tid; i < 64 * TK; i += 256) {
            int m = i / TK, k = i % TK;
            int gm = bm + m, gk = k0 + k;
            As[k][m] = (gm < M && gk < K) ? A[(size_t)gm * K + gk] : 0.f;
        }
        #pragma unroll
        for (int i = tid; i < 64 * TK; i += 256) {
            int n = i / TK, k = i % TK;
            int gn = bn + n, gk = k0 + k;
            Bs[k][n] = (gn < N && gk < K) ? Bm[(size_t)gn * K + gk] : 0.f;
        }
        __syncthreads();
        #pragma unroll
        for (int kk = 0; kk < TK; kk++) {
            float a[4], b[4];
            #pragma unroll
            for (int i = 0; i < 4; i++) a[i] = As[kk][tm * 4 + i];
            #pragma unroll
            for (int j = 0; j < 4; j++) b[j] = Bs[kk][tn * 4 + j];
            #pragma unroll
            for (int i = 0; i < 4; i++)
                #pragma unroll
                for (int j = 0; j < 4; j++)
                    acc[i][j] = fmaf(a[i], b[j], acc[i][j]);
        }
        __syncthreads();
    }
    #pragma unroll
    for (int i = 0; i < 4; i++) {
        int gm = bm + tm * 4 + i;
        if (gm >= M) continue;
        #pragma unroll
        for (int j = 0; j < 4; j++) {
            int gn = bn + tn * 4 + j;
            if (gn >= N) continue;
            float v = acc[i][j] + bias[gn];
            if (ACT == 1) v = v > 0.f ? v : 0.1f * v;
            else if (ACT == 2) v = softplus_(v) + 1e-4f;
            C[(size_t)gm * N + gn] = v;
        }
    }
}

// ---------------- zero fill ----------------
__global__ void k_zero(float* p, int n) {
    int i = blockIdx.x * blockDim.x + threadIdx.x;
    if (i < n) p[i] = 0.f;
}

// ---------------- GRU gate fuse (encoder: gi precomputed) ----------------
// giB points at g_gi + t*G3; per-batch stride is T*G3. hseqB = seq + t*H, stride T*H.
__global__ void k_gru_gate(const float* __restrict__ giB, const float* __restrict__ gh,
                           float* __restrict__ hprev, float* __restrict__ hseqB) {
    int idx = blockIdx.x * blockDim.x + threadIdx.x;
    if (idx >= BB * HH) return;
    int b = idx / HH, j = idx - b * HH;
    const float* gib = giB + (size_t)b * TT * G3;
    const float* ghb = gh + (size_t)b * G3;
    float r = sigm_(gib[j] + ghb[j]);
    float zg = sigm_(gib[HH + j] + ghb[HH + j]);
    float n = tanhf(gib[2 * HH + j] + r * ghb[2 * HH + j]);
    float hp = hprev[idx];
    float hn = (1.f - zg) * n + zg * hp;
    hprev[idx] = hn;
    hseqB[(size_t)b * TT * HH + j] = hn;
}

// ---------------- GRU gate fuse (decoder: gi computed inline, K=Z=3) ----------------
// zfB points at z_fin + t*Z; per-batch stride T*Z.
__global__ void k_gru_gate_dec(const float* __restrict__ zfB,
                               const float* __restrict__ Wih, const float* __restrict__ bih,
                               const float* __restrict__ gh,
                               float* __restrict__ hprev, float* __restrict__ hseqB) {
    int idx = blockIdx.x * blockDim.x + threadIdx.x;
    if (idx >= BB * HH) return;
    int b = idx / HH, j = idx - b * HH;
    const float* zb = zfB + (size_t)b * TT * ZZ;
    float z0 = zb[0], z1 = zb[1], z2 = zb[2];
    const float* ghb = gh + (size_t)b * G3;
    int jr = j, jz = HH + j, jn = 2 * HH + j;
    float gir = bih[jr] + Wih[3 * jr] * z0 + Wih[3 * jr + 1] * z1 + Wih[3 * jr + 2] * z2;
    float giz = bih[jz] + Wih[3 * jz] * z0 + Wih[3 * jz + 1] * z1 + Wih[3 * jz + 2] * z2;
    float gin = bih[jn] + Wih[3 * jn] * z0 + Wih[3 * jn + 1] * z1 + Wih[3 * jn + 2] * z2;
    float r = sigm_(gir + ghb[jr]);
    float zg = sigm_(giz + ghb[jz]);
    float n = tanhf(gin + r * ghb[jn]);
    float hp = hprev[idx];
    float hn = (1.f - zg) * n + zg * hp;
    hprev[idx] = hn;
    hseqB[(size_t)b * TT * HH + j] = hn;
}

// ---------------- latent scan: one block per batch element, loop over T ----------------
// inp = concat(h_t[500], z_prev[3]); mu = inp @ zmW^T + zmb; std = softplus(inp @ zsW^T + zsb)+1e-4
__global__ void k_latent(const float* __restrict__ hpost, const float* __restrict__ eps,
                         const float* __restrict__ zmW, const float* __restrict__ zmb,
                         const float* __restrict__ zsW, const float* __restrict__ zsb,
                         float* __restrict__ zg, float* __restrict__ zm, float* __restrict__ zs) {
    int b = blockIdx.x;
    __shared__ float red[6];
    __shared__ float zprev[ZZ];
    int tid = threadIdx.x;           // 192 = 6 warps
    int w = tid >> 5, lane = tid & 31;
    if (tid < ZZ) zprev[tid] = 0.f;
    __syncthreads();
    const float* Wrow = (w < 3) ? (zmW + (size_t)w * (HH + ZZ)) : (zsW + (size_t)(w - 3) * (HH + ZZ));
    for (int t = 0; t < TT; t++) {
        const float* hrow = hpost + ((size_t)b * TT + t) * HH;
        float s = 0.f;
        for (int k = lane; k < HH; k += 32) s += hrow[k] * Wrow[k];
        if (lane < ZZ) s += zprev[lane] * Wrow[HH + lane];
        #pragma unroll
        for (int o = 16; o; o >>= 1) s += __shfl_down_sync(0xffffffffu, s, o);
        if (lane == 0) red[w] = s;
        __syncthreads();
        if (tid < ZZ) {
            float mu = red[tid] + zmb[tid];
            float sd = softplus_(red[3 + tid] + zsb[tid]) + 1e-4f;
            size_t o = ((size_t)b * TT + t) * ZZ + tid;
            float zt = mu + sd * eps[o];
            zg[o] = zt; zm[o] = mu; zs[o] = sd;
            zprev[tid] = zt;
        }
        __syncthreads();
    }
}

// ---------------- planar flow stack (elementwise over B*T) ----------------
__global__ void k_flow(const float* __restrict__ zgen,
                       const float* __restrict__ fw, const float* __restrict__ fb,
                       const float* __restrict__ fu,
                       float* __restrict__ zfin, float* __restrict__ ldj) {
    __shared__ float s_uh[LL][ZZ], s_w[LL][ZZ], s_b[LL], s_uhw[LL];
    int tid = threadIdx.x;
    if (tid < LL) {
        float w0 = fw[tid * 3], w1 = fw[tid * 3 + 1], w2 = fw[tid * 3 + 2];
        float u0 = fu[tid * 3], u1 = fu[tid * 3 + 1], u2 = fu[tid * 3 + 2];
        float wu = w0 * u0 + w1 * u1 + w2 * u2;
        float m = -1.f + softplus_(wu);
        float c = (m - wu) / (w0 * w0 + w1 * w1 + w2 * w2 + 1e-7f);
        float uh0 = u0 + c * w0, uh1 = u1 + c * w1, uh2 = u2 + c * w2;
        s_uh[tid][0] = uh0; s_uh[tid][1] = uh1; s_uh[tid][2] = uh2;
        s_w[tid][0] = w0; s_w[tid][1] = w1; s_w[tid][2] = w2;
        s_b[tid] = fb[tid];
        s_uhw[tid] = uh0 * w0 + uh1 * w1 + uh2 * w2;
    }
    __syncthreads();
    int idx = blockIdx.x * blockDim.x + tid;
    if (idx >= BT) return;
    float z0 = zgen[idx * 3], z1 = zgen[idx * 3 + 1], z2 = zgen[idx * 3 + 2];
    float ld = 0.f;
    #pragma unroll
    for (int l = 0; l < LL; l++) {
        float lin = z0 * s_w[l][0] + z1 * s_w[l][1] + z2 * s_w[l][2] + s_b[l];
        float t = tanhf(lin);
        z0 += s_uh[l][0] * t; z1 += s_uh[l][1] * t; z2 += s_uh[l][2] * t;
        float det = 1.f + (1.f - t * t) * s_uhw[l];
        ld += logf(fabsf(det) + 1e-7f);
    }
    zfin[idx * 3] = z0; zfin[idx * 3 + 1] = z1; zfin[idx * 3 + 2] = z2;
    ldj[idx] = ld;
}

// ---------------- launch ----------------
extern "C" void kernel_launch(void* const* d_in, const int* in_sizes, int n_in,
                              void* d_out, int out_size) {
    const float* x       = (const float*)d_in[0];
    const float* eps     = (const float*)d_in[1];
    const float* enc_Wih = (const float*)d_in[2];
    const float* enc_Whh = (const float*)d_in[3];
    const float* enc_bih = (const float*)d_in[4];
    const float* enc_bhh = (const float*)d_in[5];
    const float* enc_W1  = (const float*)d_in[6];
    const float* enc_b1  = (const float*)d_in[7];
    const float* enc_W2  = (const float*)d_in[8];
    const float* enc_b2  = (const float*)d_in[9];
    const float* zm_W    = (const float*)d_in[10];
    const float* zm_b    = (const float*)d_in[11];
    const float* zs_W    = (const float*)d_in[12];
    const float* zs_b    = (const float*)d_in[13];
    const float* flow_w  = (const float*)d_in[14];
    const float* flow_b  = (const float*)d_in[15];
    const float* flow_u  = (const float*)d_in[16];
    const float* dec_Wih = (const float*)d_in[17];
    const float* dec_Whh = (const float*)d_in[18];
    const float* dec_bih = (const float*)d_in[19];
    const float* dec_bhh = (const float*)d_in[20];
    const float* dec_W1  = (const float*)d_in[21];
    const float* dec_b1  = (const float*)d_in[22];
    const float* dec_W2  = (const float*)d_in[23];
    const float* dec_b2  = (const float*)d_in[24];
    const float* xm_W    = (const float*)d_in[25];
    const float* xm_b    = (const float*)d_in[26];
    const float* xs_W    = (const float*)d_in[27];
    const float* xs_b    = (const float*)d_in[28];

    float *gi, *seq1, *seq2, *gh, *hprev;
    cudaGetSymbolAddress((void**)&gi, g_gi);
    cudaGetSymbolAddress((void**)&seq1, g_seq1);
    cudaGetSymbolAddress((void**)&seq2, g_seq2);
    cudaGetSymbolAddress((void**)&gh, g_gh);
    cudaGetSymbolAddress((void**)&hprev, g_hprev);

    float* out  = (float*)d_out;
    float* o_mu = out;                              // [B,T,X]
    float* o_sd = o_mu + (size_t)BT * XX;           // [B,T,X]
    float* o_zg = o_sd + (size_t)BT * XX;           // [B,T,Z]
    float* o_zf = o_zg + (size_t)BT * ZZ;           // [B,T,Z]
    float* o_zm = o_zf + (size_t)BT * ZZ;           // [B,T,Z]
    float* o_zs = o_zm + (size_t)BT * ZZ;           // [B,T,Z]
    float* o_ld = o_zs + (size_t)BT * ZZ;           // [B,T,1]

    const int BHn = BB * HH;
    const dim3 gGi((G3 + 63) / 64, (BT + 63) / 64);      // 24 x 800
    const dim3 gStep((G3 + 63) / 64, (BB + 63) / 64);    // 24 x 8
    const dim3 gPost((HH + 63) / 64, (BT + 63) / 64);    // 8 x 800
    const dim3 gProj((XX + 63) / 64, (BT + 63) / 64);    // 1 x 800

    // ---- Encoder ----
    gemm_abt<0><<<gGi, 256>>>(x, enc_Wih, enc_bih, gi, BT, G3, XX);
    k_zero<<<(BHn + 255) / 256, 256>>>(hprev, BHn);
    for (int t = 0; t < TT; t++) {
        gemm_abt<0><<<gStep, 256>>>(hprev, enc_Whh, enc_bhh, gh, BB, G3, HH);
        k_gru_gate<<<(BHn + 255) / 256, 256>>>(gi + (size_t)t * G3, gh, hprev,
                                               seq1 + (size_t)t * HH);
    }
    gemm_abt<1><<<gPost, 256>>>(seq1, enc_W1, enc_b1, seq2, BT, HH, HH);
    gemm_abt<1><<<gPost, 256>>>(seq2, enc_W2, enc_b2, seq1, BT, HH, HH);

    // ---- Latent scan + flows ----
    k_latent<<<BB, 192>>>(seq1, eps, zm_W, zm_b, zs_W, zs_b, o_zg, o_zm, o_zs);
    k_flow<<<(BT + 255) / 256, 256>>>(o_zg, flow_w, flow_b, flow_u, o_zf, o_ld);

    // ---- Decoder ----
    k_zero<<<(BHn + 255) / 256, 256>>>(hprev, BHn);
    for (int t = 0; t < TT; t++) {
        gemm_abt<0><<<gStep, 256>>>(hprev, dec_Whh, dec_bhh, gh, BB, G3, HH);
        k_gru_gate_dec<<<(BHn + 255) / 256, 256>>>(o_zf + (size_t)t * ZZ, dec_Wih, dec_bih,
                                                   gh, hprev, seq2 + (size_t)t * HH);
    }
    gemm_abt<1><<<gPost, 256>>>(seq2, dec_W1, dec_b1, seq1, BT, HH, HH);
    gemm_abt<1><<<gPost, 256>>>(seq1, dec_W2, dec_b2, seq2, BT, HH, HH);

    // ---- Output projections ----
    gemm_abt<0><<<gProj, 256>>>(seq2, xm_W, xm_b, o_mu, BT, XX, HH);
    gemm_abt<2><<<gProj, 256>>>(seq2, xs_W, xs_b, o_sd, BT, XX, HH);
}

// round 2
// speedup vs baseline: 2.2852x; 2.2852x over previous
#include <cuda_runtime.h>
#include <math.h>

// ---------------- problem dims ----------------
#define BB  512
#define TT  100
#define XX  38
#define ZZ  3
#define HH  500
#define LL  20
#define G3  (3*HH)      // 1500
#define BT  (BB*TT)     // 51200

// ---- persistent GRU tiling ----
#define NBLK   144      // 4 M-tiles x 36 J-tiles; <= SM count (148/152) so all resident
#define MT_    4
#define JT_    36
#define MTILE  128
#define JTILE  14
#define CTILE  42       // 3 * JTILE (r/z/n column groups)
#define WS_ROWS 504     // 500 padded to mult of 8
#define WS_PITCH 48
#define CS_PITCH 44

// ---------------- scratch (__device__ globals; no allocation allowed) ----------------
__device__ float g_gi[(size_t)BT * G3];    // encoder input-gates  [B,T,3H]
__device__ float g_seq1[(size_t)BT * HH];  // seq buffer A         [B,T,H]
__device__ float g_seq2[(size_t)BT * HH];  // seq buffer B         [B,T,H]
__device__ unsigned g_cnt = 0;             // grid barrier arrival counter
__device__ unsigned g_sense = 0;           // grid barrier generation (monotonic)

// ---------------- helpers ----------------
__device__ __forceinline__ float sigm_(float x) { return 1.f / (1.f + expf(-x)); }
__device__ __forceinline__ float softplus_(float x) { return x > 15.f ? x : log1pf(expf(x)); }

// ---------------- software grid barrier (grid must be exactly NBLK CTAs) ----------------
__device__ __forceinline__ void gsync(unsigned gen, unsigned base) {
    __syncthreads();
    if (threadIdx.x == 0) {
        __threadfence();
        unsigned a = atomicAdd(&g_cnt, 1);
        if (a == NBLK - 1) {
            g_cnt = 0;
            __threadfence();
            *(volatile unsigned*)&g_sense = base + gen;
        } else {
            while ((unsigned)(*(volatile unsigned*)&g_sense - base) < gen) {}
        }
        __threadfence();
    }
    __syncthreads();
}

// ---------------- persistent GRU: weight-stationary, 1 barrier per timestep ----------------
// DEC=0: giz = precomputed input gates [B,T,3H] (incl. bih). DEC=1: giz = z_fin [B,T,3], gates inline.
template<int DEC>
__global__ void __launch_bounds__(256, 1)
k_gru(const float* __restrict__ giz,
      const float* __restrict__ Wih, const float* __restrict__ bih,
      const float* __restrict__ Whh, const float* __restrict__ bhh,
      float* __restrict__ seq) {
    extern __shared__ float sm[];
    float* Ws = sm;                                  // [WS_ROWS][WS_PITCH]
    float* As = Ws + WS_ROWS * WS_PITCH;             // [8][128]
    float* Cs = As + 8 * 128;                        // [128][CS_PITCH]

    const int blk = blockIdx.x;
    const int mt = blk / JT_, jt = blk - mt * JT_;
    const int bm = mt * MTILE;
    const int jbase = jt * JTILE;
    const int tid = threadIdx.x;
    const int tm = tid >> 4, tn = tid & 15;
    const int lm = tid >> 1, kq = (tid & 1) * 4;

    // Load Whh slice into SMEM: Ws[k][c], c = gate*JTILE + jj -> Whh row gate*500 + jbase+jj
    for (int i = tid; i < WS_ROWS * WS_PITCH; i += 256) Ws[i] = 0.f;
    __syncthreads();
    for (int i = tid; i < CTILE * HH; i += 256) {
        int c = i / HH, k = i - c * HH;
        int jj = c % JTILE, gate = c / JTILE;
        int j = jbase + jj;
        if (j < HH) Ws[k * WS_PITCH + c] = Whh[(size_t)(gate * HH + j) * HH + k];
    }
    __syncthreads();

    unsigned base = *(volatile unsigned*)&g_sense;

    for (int t = 0; t < TT; t++) {
        float acc[8][3] = {};
        if (t > 0) {
            const float* hp = seq + ((size_t)(bm + lm) * TT + (t - 1)) * HH + kq;
            for (int k0 = 0; k0 < HH; k0 += 8) {
                int kc = HH - k0;
                #pragma unroll
                for (int q = 0; q < 4; q++)
                    As[(kq + q) * 128 + lm] = (kq + q < kc) ? hp[k0 + q] : 0.f;
                __syncthreads();
                #pragma unroll
                for (int kk = 0; kk < 8; kk++) {
                    float4 a0 = *(const float4*)&As[kk * 128 + tm * 8];
                    float4 a1 = *(const float4*)&As[kk * 128 + tm * 8 + 4];
                    const float* wr = &Ws[(k0 + kk) * WS_PITCH + tn * 3];
                    float b0 = wr[0], b1 = wr[1], b2 = wr[2];
                    float a[8] = {a0.x, a0.y, a0.z, a0.w, a1.x, a1.y, a1.z, a1.w};
                    #pragma unroll
                    for (int i = 0; i < 8; i++) {
                        acc[i][0] = fmaf(a[i], b0, acc[i][0]);
                        acc[i][1] = fmaf(a[i], b1, acc[i][1]);
                        acc[i][2] = fmaf(a[i], b2, acc[i][2]);
                    }
                }
                __syncthreads();
            }
        }
        // stash hidden-gate tile to SMEM (cols >= CTILE discarded)
        #pragma unroll
        for (int i = 0; i < 8; i++) {
            #pragma unroll
            for (int jj = 0; jj < 3; jj++) {
                int col = tn * 3 + jj;
                if (col < CTILE) Cs[(tm * 8 + i) * CS_PITCH + col] = acc[i][jj];
            }
        }
        __syncthreads();
        // local gate phase: units (m in [0,128), jj in [0,JTILE))
        for (int u = tid; u < MTILE * JTILE; u += 256) {
            int m = u / JTILE, jj = u - (u / JTILE) * JTILE;
            int j = jbase + jj;
            if (j < HH) {
                int b = bm + m;
                float ghr = Cs[m * CS_PITCH + jj]              + bhh[j];
                float ghz = Cs[m * CS_PITCH + JTILE + jj]      + bhh[HH + j];
                float ghn = Cs[m * CS_PITCH + 2 * JTILE + jj]  + bhh[2 * HH + j];
                float gir, gzv, gin;
                if (DEC) {
                    const float* zb = giz + ((size_t)b * TT + t) * ZZ;
                    float z0 = zb[0], z1 = zb[1], z2 = zb[2];
                    int jr = j, jz = HH + j, jn = 2 * HH + j;
                    gir = bih[jr] + Wih[3*jr]*z0 + Wih[3*jr+1]*z1 + Wih[3*jr+2]*z2;
                    gzv = bih[jz] + Wih[3*jz]*z0 + Wih[3*jz+1]*z1 + Wih[3*jz+2]*z2;
                    gin = bih[jn] + Wih[3*jn]*z0 + Wih[3*jn+1]*z1 + Wih[3*jn+2]*z2;
                } else {
                    const float* gb = giz + ((size_t)b * TT + t) * G3;
                    gir = gb[j]; gzv = gb[HH + j]; gin = gb[2 * HH + j];
                }
                float r  = sigm_(gir + ghr);
                float zg = sigm_(gzv + ghz);
                float n  = tanhf(gin + r * ghn);
                float hpv = (t == 0) ? 0.f : seq[((size_t)b * TT + (t - 1)) * HH + j];
                seq[((size_t)b * TT + t) * HH + j] = (1.f - zg) * n + zg * hpv;
            }
        }
        gsync(t + 1, base);
    }
}

// ---------------- 128x128-tile GEMM: C[M,N] = act(A[M,K] * W[N,K]^T + bias[N]) ----------------
// ACT: 0 none, 1 leaky_relu(0.1), 2 softplus+1e-4.  Requires N % 4 == 0 for vector stores (500/1500 ok).
template<int ACT>
__global__ void __launch_bounds__(256, 2)
gemm128(const float* __restrict__ A, const float* __restrict__ W,
        const float* __restrict__ bias, float* __restrict__ C,
        int M, int N, int K) {
    __shared__ float As[8][132], Bs[8][132];
    const int bn = blockIdx.x * 128, bm = blockIdx.y * 128;
    const int tid = threadIdx.x, tm = tid >> 4, tn = tid & 15;
    const int lr = tid >> 1, kq = (tid & 1) * 4;
    float acc[8][8] = {};
    for (int k0 = 0; k0 < K; k0 += 8) {
        #pragma unroll
        for (int q = 0; q < 4; q++) {
            int k = k0 + kq + q;
            As[kq + q][lr] = (k < K && bm + lr < M) ? A[(size_t)(bm + lr) * K + k] : 0.f;
            Bs[kq + q][lr] = (k < K && bn + lr < N) ? W[(size_t)(bn + lr) * K + k] : 0.f;
        }
        __syncthreads();
        #pragma unroll
        for (int kk = 0; kk < 8; kk++) {
            float a[8], b[8];
            *(float4*)&a[0] = *(const float4*)&As[kk][tm * 8];
            *(float4*)&a[4] = *(const float4*)&As[kk][tm * 8 + 4];
            *(float4*)&b[0] = *(const float4*)&Bs[kk][tn * 8];
            *(float4*)&b[4] = *(const float4*)&Bs[kk][tn * 8 + 4];
            #pragma unroll
            for (int i = 0; i < 8; i++)
                #pragma unroll
                for (int j = 0; j < 8; j++)
                    acc[i][j] = fmaf(a[i], b[j], acc[i][j]);
        }
        __syncthreads();
    }
    #pragma unroll
    for (int i = 0; i < 8; i++) {
        int gm = bm + tm * 8 + i;
        if (gm >= M) break;
        float v[8];
        #pragma unroll
        for (int j = 0; j < 8; j++) {
            int gn = bn + tn * 8 + j;
            float tv = acc[i][j] + ((gn < N) ? bias[gn] : 0.f);
            if (ACT == 1) tv = tv > 0.f ? tv : 0.1f * tv;
            else if (ACT == 2) tv = softplus_(tv) + 1e-4f;
            v[j] = tv;
        }
        if (bn + tn * 8 + 8 <= N) {
            float4* dst = (float4*)&C[(size_t)gm * N + bn + tn * 8];
            dst[0] = *(float4*)&v[0];
            dst[1] = *(float4*)&v[4];
        } else {
            #pragma unroll
            for (int j = 0; j < 8; j++) {
                int gn = bn + tn * 8 + j;
                if (gn < N) C[(size_t)gm * N + gn] = v[j];
            }
        }
    }
}

// ---------------- small-N GEMM for output projections (N=38) ----------------
#define TK 16
template <int ACT>
__global__ void gemm_abt(const float* __restrict__ A, const float* __restrict__ Bm,
                         const float* __restrict__ bias, float* __restrict__ C,
                         int M, int N, int K) {
    __shared__ float As[TK][64];
    __shared__ float Bs[TK][64];
    const int bn = blockIdx.x * 64;
    const int bm = blockIdx.y * 64;
    const int tid = threadIdx.x;
    const int tm = tid >> 4, tn = tid & 15;
    float acc[4][4] = {};
    for (int k0 = 0; k0 < K; k0 += TK) {
        #pragma unroll
        for (int i = tid; i < 64 * TK; i += 256) {
            int m = i / TK, k = i % TK;
            int gm = bm + m, gk = k0 + k;
            As[k][m] = (gm < M && gk < K) ? A[(size_t)gm * K + gk] : 0.f;
        }
        #pragma unroll
        for (int i = tid; i < 64 * TK; i += 256) {
            int n = i / TK, k = i % TK;
            int gn = bn + n, gk = k0 + k;
            Bs[k][n] = (gn < N && gk < K) ? Bm[(size_t)gn * K + gk] : 0.f;
        }
        __syncthreads();
        #pragma unroll
        for (int kk = 0; kk < TK; kk++) {
            float a[4], b[4];
            #pragma unroll
            for (int i = 0; i < 4; i++) a[i] = As[kk][tm * 4 + i];
            #pragma unroll
            for (int j = 0; j < 4; j++) b[j] = Bs[kk][tn * 4 + j];
            #pragma unroll
            for (int i = 0; i < 4; i++)
                #pragma unroll
                for (int j = 0; j < 4; j++)
                    acc[i][j] = fmaf(a[i], b[j], acc[i][j]);
        }
        __syncthreads();
    }
    #pragma unroll
    for (int i = 0; i < 4; i++) {
        int gm = bm + tm * 4 + i;
        if (gm >= M) continue;
        #pragma unroll
        for (int j = 0; j < 4; j++) {
            int gn = bn + tn * 4 + j;
            if (gn >= N) continue;
            float v = acc[i][j] + bias[gn];
            if (ACT == 1) v = v > 0.f ? v : 0.1f * v;
            else if (ACT == 2) v = softplus_(v) + 1e-4f;
            C[(size_t)gm * N + gn] = v;
        }
    }
}

// ---------------- latent scan: one block per batch element, loop over T ----------------
__global__ void k_latent(const float* __restrict__ hpost, const float* __restrict__ eps,
                         const float* __restrict__ zmW, const float* __restrict__ zmb,
                         const float* __restrict__ zsW, const float* __restrict__ zsb,
                         float* __restrict__ zg, float* __restrict__ zm, float* __restrict__ zs) {
    int b = blockIdx.x;
    __shared__ float red[6];
    __shared__ float zprev[ZZ];
    int tid = threadIdx.x;           // 192 = 6 warps
    int w = tid >> 5, lane = tid & 31;
    if (tid < ZZ) zprev[tid] = 0.f;
    __syncthreads();
    const float* Wrow = (w < 3) ? (zmW + (size_t)w * (HH + ZZ)) : (zsW + (size_t)(w - 3) * (HH + ZZ));
    for (int t = 0; t < TT; t++) {
        const float* hrow = hpost + ((size_t)b * TT + t) * HH;
        float s = 0.f;
        for (int k = lane; k < HH; k += 32) s += hrow[k] * Wrow[k];
        if (lane < ZZ) s += zprev[lane] * Wrow[HH + lane];
        #pragma unroll
        for (int o = 16; o; o >>= 1) s += __shfl_down_sync(0xffffffffu, s, o);
        if (lane == 0) red[w] = s;
        __syncthreads();
        if (tid < ZZ) {
            float mu = red[tid] + zmb[tid];
            float sd = softplus_(red[3 + tid] + zsb[tid]) + 1e-4f;
            size_t o = ((size_t)b * TT + t) * ZZ + tid;
            float zt = mu + sd * eps[o];
            zg[o] = zt; zm[o] = mu; zs[o] = sd;
            zprev[tid] = zt;
        }
        __syncthreads();
    }
}

// ---------------- planar flow stack (elementwise over B*T) ----------------
__global__ void k_flow(const float* __restrict__ zgen,
                       const float* __restrict__ fw, const float* __restrict__ fb,
                       const float* __restrict__ fu,
                       float* __restrict__ zfin, float* __restrict__ ldj) {
    __shared__ float s_uh[LL][ZZ], s_w[LL][ZZ], s_b[LL], s_uhw[LL];
    int tid = threadIdx.x;
    if (tid < LL) {
        float w0 = fw[tid * 3], w1 = fw[tid * 3 + 1], w2 = fw[tid * 3 + 2];
        float u0 = fu[tid * 3], u1 = fu[tid * 3 + 1], u2 = fu[tid * 3 + 2];
        float wu = w0 * u0 + w1 * u1 + w2 * u2;
        float m = -1.f + softplus_(wu);
        float c = (m - wu) / (w0 * w0 + w1 * w1 + w2 * w2 + 1e-7f);
        float uh0 = u0 + c * w0, uh1 = u1 + c * w1, uh2 = u2 + c * w2;
        s_uh[tid][0] = uh0; s_uh[tid][1] = uh1; s_uh[tid][2] = uh2;
        s_w[tid][0] = w0; s_w[tid][1] = w1; s_w[tid][2] = w2;
        s_b[tid] = fb[tid];
        s_uhw[tid] = uh0 * w0 + uh1 * w1 + uh2 * w2;
    }
    __syncthreads();
    int idx = blockIdx.x * blockDim.x + tid;
    if (idx >= BT) return;
    float z0 = zgen[idx * 3], z1 = zgen[idx * 3 + 1], z2 = zgen[idx * 3 + 2];
    float ld = 0.f;
    #pragma unroll
    for (int l = 0; l < LL; l++) {
        float lin = z0 * s_w[l][0] + z1 * s_w[l][1] + z2 * s_w[l][2] + s_b[l];
        float t = tanhf(lin);
        z0 += s_uh[l][0] * t; z1 += s_uh[l][1] * t; z2 += s_uh[l][2] * t;
        float det = 1.f + (1.f - t * t) * s_uhw[l];
        ld += logf(fabsf(det) + 1e-7f);
    }
    zfin[idx * 3] = z0; zfin[idx * 3 + 1] = z1; zfin[idx * 3 + 2] = z2;
    ldj[idx] = ld;
}

// ---------------- launch ----------------
extern "C" void kernel_launch(void* const* d_in, const int* in_sizes, int n_in,
                              void* d_out, int out_size) {
    const float* x       = (const float*)d_in[0];
    const float* eps     = (const float*)d_in[1];
    const float* enc_Wih = (const float*)d_in[2];
    const float* enc_Whh = (const float*)d_in[3];
    const float* enc_bih = (const float*)d_in[4];
    const float* enc_bhh = (const float*)d_in[5];
    const float* enc_W1  = (const float*)d_in[6];
    const float* enc_b1  = (const float*)d_in[7];
    const float* enc_W2  = (const float*)d_in[8];
    const float* enc_b2  = (const float*)d_in[9];
    const float* zm_W    = (const float*)d_in[10];
    const float* zm_b    = (const float*)d_in[11];
    const float* zs_W    = (const float*)d_in[12];
    const float* zs_b    = (const float*)d_in[13];
    const float* flow_w  = (const float*)d_in[14];
    const float* flow_b  = (const float*)d_in[15];
    const float* flow_u  = (const float*)d_in[16];
    const float* dec_Wih = (const float*)d_in[17];
    const float* dec_Whh = (const float*)d_in[18];
    const float* dec_bih = (const float*)d_in[19];
    const float* dec_bhh = (const float*)d_in[20];
    const float* dec_W1  = (const float*)d_in[21];
    const float* dec_b1  = (const float*)d_in[22];
    const float* dec_W2  = (const float*)d_in[23];
    const float* dec_b2  = (const float*)d_in[24];
    const float* xm_W    = (const float*)d_in[25];
    const float* xm_b    = (const float*)d_in[26];
    const float* xs_W    = (const float*)d_in[27];
    const float* xs_b    = (const float*)d_in[28];

    float *gi, *seq1, *seq2;
    cudaGetSymbolAddress((void**)&gi, g_gi);
    cudaGetSymbolAddress((void**)&seq1, g_seq1);
    cudaGetSymbolAddress((void**)&seq2, g_seq2);

    float* out  = (float*)d_out;
    float* o_mu = out;                              // [B,T,X]
    float* o_sd = o_mu + (size_t)BT * XX;           // [B,T,X]
    float* o_zg = o_sd + (size_t)BT * XX;           // [B,T,Z]
    float* o_zf = o_zg + (size_t)BT * ZZ;           // [B,T,Z]
    float* o_zm = o_zf + (size_t)BT * ZZ;           // [B,T,Z]
    float* o_zs = o_zm + (size_t)BT * ZZ;           // [B,T,Z]
    float* o_ld = o_zs + (size_t)BT * ZZ;           // [B,T,1]

    const int SMEMB = (WS_ROWS * WS_PITCH + 8 * 128 + 128 * CS_PITCH) * 4;  // ~123 KB
    static bool attr_done = false;
    if (!attr_done) {
        cudaFuncSetAttribute(k_gru<0>, cudaFuncAttributeMaxDynamicSharedMemorySize, SMEMB);
        cudaFuncSetAttribute(k_gru<1>, cudaFuncAttributeMaxDynamicSharedMemorySize, SMEMB);
        attr_done = true;
    }

    const dim3 gGi((G3 + 127) / 128, (BT + 127) / 128);    // 12 x 400
    const dim3 gPost((HH + 127) / 128, (BT + 127) / 128);  // 4 x 400
    const dim3 gProj((XX + 63) / 64, (BT + 63) / 64);      // 1 x 800

    // ---- Encoder ----
    gemm128<0><<<gGi, 256>>>(x, enc_Wih, enc_bih, gi, BT, G3, XX);
    k_gru<0><<<NBLK, 256, SMEMB>>>(gi, nullptr, nullptr, enc_Whh, enc_bhh, seq1);
    gemm128<1><<<gPost, 256>>>(seq1, enc_W1, enc_b1, seq2, BT, HH, HH);
    gemm128<1><<<gPost, 256>>>(seq2, enc_W2, enc_b2, seq1, BT, HH, HH);

    // ---- Latent scan + flows ----
    k_latent<<<BB, 192>>>(seq1, eps, zm_W, zm_b, zs_W, zs_b, o_zg, o_zm, o_zs);
    k_flow<<<(BT + 255) / 256, 256>>>(o_zg, flow_w, flow_b, flow_u, o_zf, o_ld);

    // ---- Decoder ----
    k_gru<1><<<NBLK, 256, SMEMB>>>(o_zf, dec_Wih, dec_bih, dec_Whh, dec_bhh, seq2);
    gemm128<1><<<gPost, 256>>>(seq2, dec_W1, dec_b1, seq1, BT, HH, HH);
    gemm128<1><<<gPost, 256>>>(seq1, dec_W2, dec_b2, seq2, BT, HH, HH);

    // ---- Output projections ----
    gemm_abt<0><<<gProj, 256>>>(seq2, xm_W, xm_b, o_mu, BT, XX, HH);
    gemm_abt<2><<<gProj, 256>>>(seq2, xs_W, xs_b, o_sd, BT, XX, HH);
}

// round 3
// speedup vs baseline: 4.5012x; 1.9698x over previous
#include <cuda_runtime.h>
#include <math.h>

// ---------------- problem dims ----------------
#define BB  512
#define TT  100
#define XX  38
#define ZZ  3
#define HH  500
#define LL  20
#define G3  (3*HH)      // 1500
#define BT  (BB*TT)     // 51200

// ---- persistent GRU tiling (tensor core) ----
#define NBLK   128      // 4 M-tiles x 32 J-tiles
#define JT_    32
#define MTILE  128
#define JTILE  16
#define CTILE  48       // 3 gates * JTILE
#define WPITCH 516      // Ws k-pitch (conflict-free, holds k up to 512)
#define APITCH 136      // As m-pitch (conflict-free)
#define CPITCH 52       // Cs col-pitch
#define GRU_BK 32

// ---------------- scratch ----------------
__device__ float g_gi[(size_t)BT * G3];    // encoder input-gates [B,T,3H]
__device__ float g_seq1[(size_t)BT * HH];
__device__ float g_seq2[(size_t)BT * HH];
__device__ unsigned g_cnt = 0;
__device__ unsigned g_sense = 0;

// ---------------- helpers ----------------
__device__ __forceinline__ float sigm_(float x) { return 1.f / (1.f + expf(-x)); }
__device__ __forceinline__ float softplus_(float x) { return x > 15.f ? x : log1pf(expf(x)); }
__device__ __forceinline__ float f2tf(float f) {
    unsigned u; asm("cvt.rna.tf32.f32 %0, %1;" : "=r"(u) : "f"(f));
    return __uint_as_float(u);
}
__device__ __forceinline__ void mma_tf32(float* c, const unsigned* a, const unsigned* b) {
    asm volatile("mma.sync.aligned.m16n8k8.row.col.f32.tf32.tf32.f32 "
        "{%0,%1,%2,%3}, {%4,%5,%6,%7}, {%8,%9}, {%0,%1,%2,%3};\n"
        : "+f"(c[0]), "+f"(c[1]), "+f"(c[2]), "+f"(c[3])
        : "r"(a[0]), "r"(a[1]), "r"(a[2]), "r"(a[3]), "r"(b[0]), "r"(b[1]));
}

// ---------------- software grid barrier (grid must be exactly NBLK CTAs) ----------------
__device__ __forceinline__ void gsync(unsigned gen, unsigned base) {
    __syncthreads();
    if (threadIdx.x == 0) {
        __threadfence();
        unsigned a = atomicAdd(&g_cnt, 1);
        if (a == NBLK - 1) {
            g_cnt = 0;
            __threadfence();
            *(volatile unsigned*)&g_sense = base + gen;
        } else {
            while ((unsigned)(*(volatile unsigned*)&g_sense - base) < gen) {}
        }
        __threadfence();
    }
    __syncthreads();
}

// ---------------- persistent GRU (tf32 mma, weight-stationary) ----------------
// DEC=0: giz = input gates [B,T,3H] (incl bih). DEC=1: giz = z_fin [B,T,3], gates inline.
template<int DEC>
__global__ void __launch_bounds__(256, 1)
k_gru_tc(const float* __restrict__ giz,
         const float* __restrict__ Wih, const float* __restrict__ bih,
         const float* __restrict__ Whh, const float* __restrict__ bhh,
         float* __restrict__ seq) {
    extern __shared__ float sm[];
    float* Ws = sm;                                  // [CTILE][WPITCH]
    float* As = Ws + CTILE * WPITCH;                 // [GRU_BK][APITCH]
    float* Cs = As + GRU_BK * APITCH;                // [128][CPITCH]

    const int blk = blockIdx.x;
    const int mt = blk >> 5, jt = blk & 31;          // 4 x 32
    const int bm = mt * MTILE;
    const int jbase = jt * JTILE;
    const int tid = threadIdx.x;
    const int warp = tid >> 5, lane = tid & 31;
    const int wm = warp >> 1, wn = warp & 1;         // warp tile: m32 x n24
    const int gq = lane >> 2, lt = lane & 3;

    // ---- load Whh slice (tf32) into Ws[c][k]; zero pad k in [500,512) and j>=HH ----
    for (int i = tid; i < CTILE * 512; i += 256) {
        int c = i >> 9, k = i & 511;
        int gate = c >> 4, jj = c & 15;
        int j = jbase + jj;
        float v = 0.f;
        if (j < HH && k < HH) v = f2tf(Whh[(size_t)(gate * HH + j) * HH + k]);
        Ws[c * WPITCH + k] = v;
    }
    __syncthreads();

    unsigned base = *(volatile unsigned*)&g_sense;
    const int m_ = tid >> 1, kq_ = (tid & 1) * 16;

    for (int t = 0; t < TT; t++) {
        float acc[2][3][4] = {};
        if (t > 0) {
            const float* hp = seq + ((size_t)(bm + m_) * TT + (t - 1)) * HH;
            for (int kbase = 0; kbase < HH; kbase += GRU_BK) {
                // fill As chunk (transposed, tf32)
                #pragma unroll
                for (int q = 0; q < 4; q++) {
                    int gk = kbase + kq_ + q * 4;
                    float4 v = make_float4(0.f, 0.f, 0.f, 0.f);
                    if (gk < HH) v = *(const float4*)(hp + gk);
                    int kk = kq_ + q * 4;
                    As[(kk + 0) * APITCH + m_] = f2tf(v.x);
                    As[(kk + 1) * APITCH + m_] = f2tf(v.y);
                    As[(kk + 2) * APITCH + m_] = f2tf(v.z);
                    As[(kk + 3) * APITCH + m_] = f2tf(v.w);
                }
                __syncthreads();
                #pragma unroll
                for (int ks = 0; ks < GRU_BK; ks += 8) {
                    unsigned a[2][4], b[3][2];
                    #pragma unroll
                    for (int mi = 0; mi < 2; mi++) {
                        int row = wm * 32 + mi * 16 + gq;
                        a[mi][0] = __float_as_uint(As[(ks + lt) * APITCH + row]);
                        a[mi][1] = __float_as_uint(As[(ks + lt) * APITCH + row + 8]);
                        a[mi][2] = __float_as_uint(As[(ks + lt + 4) * APITCH + row]);
                        a[mi][3] = __float_as_uint(As[(ks + lt + 4) * APITCH + row + 8]);
                    }
                    #pragma unroll
                    for (int ni = 0; ni < 3; ni++) {
                        int c = wn * 24 + ni * 8 + gq;
                        b[ni][0] = __float_as_uint(Ws[c * WPITCH + kbase + ks + lt]);
                        b[ni][1] = __float_as_uint(Ws[c * WPITCH + kbase + ks + lt + 4]);
                    }
                    #pragma unroll
                    for (int mi = 0; mi < 2; mi++)
                        #pragma unroll
                        for (int ni = 0; ni < 3; ni++)
                            mma_tf32(acc[mi][ni], a[mi], b[ni]);
                }
                __syncthreads();
            }
        }
        // ---- stash hidden-gate tile to Cs ----
        #pragma unroll
        for (int mi = 0; mi < 2; mi++)
            #pragma unroll
            for (int ni = 0; ni < 3; ni++) {
                int r0 = wm * 32 + mi * 16 + gq;
                int c0 = wn * 24 + ni * 8 + 2 * lt;
                *(float2*)&Cs[r0 * CPITCH + c0] = make_float2(acc[mi][ni][0], acc[mi][ni][1]);
                *(float2*)&Cs[(r0 + 8) * CPITCH + c0] = make_float2(acc[mi][ni][2], acc[mi][ni][3]);
            }
        __syncthreads();
        // ---- gate phase ----
        for (int u = tid; u < MTILE * JTILE; u += 256) {
            int m = u >> 4, jj = u & 15;
            int j = jbase + jj;
            if (j < HH) {
                int b = bm + m;
                float ghr = Cs[m * CPITCH + jj]      + bhh[j];
                float ghz = Cs[m * CPITCH + 16 + jj] + bhh[HH + j];
                float ghn = Cs[m * CPITCH + 32 + jj] + bhh[2 * HH + j];
                float gir, gzv, gin;
                if (DEC) {
                    const float* zb = giz + ((size_t)b * TT + t) * ZZ;
                    float z0 = zb[0], z1 = zb[1], z2 = zb[2];
                    int jr = j, jz = HH + j, jn = 2 * HH + j;
                    gir = bih[jr] + Wih[3*jr]*z0 + Wih[3*jr+1]*z1 + Wih[3*jr+2]*z2;
                    gzv = bih[jz] + Wih[3*jz]*z0 + Wih[3*jz+1]*z1 + Wih[3*jz+2]*z2;
                    gin = bih[jn] + Wih[3*jn]*z0 + Wih[3*jn+1]*z1 + Wih[3*jn+2]*z2;
                } else {
                    const float* gb = giz + ((size_t)b * TT + t) * G3;
                    gir = gb[j]; gzv = gb[HH + j]; gin = gb[2 * HH + j];
                }
                float r  = sigm_(gir + ghr);
                float zg = sigm_(gzv + ghz);
                float n  = tanhf(gin + r * ghn);
                float hpv = (t == 0) ? 0.f : seq[((size_t)b * TT + (t - 1)) * HH + j];
                seq[((size_t)b * TT + t) * HH + j] = (1.f - zg) * n + zg * hpv;
            }
        }
        gsync(t + 1, base);
    }
}

// ---------------- tf32 tensor-core GEMM: C[M,N] = act(A[M,K] @ W[N,K]^T + bias) ----------------
// ACT: 0 none, 1 leaky_relu(0.1), 2 softplus+1e-4. Requires N even (38/500/1500 ok).
template<int ACT>
__global__ void __launch_bounds__(256, 1)
gemm_tc(const float* __restrict__ A, const float* __restrict__ W,
        const float* __restrict__ bias, float* __restrict__ C,
        int M, int N, int K) {
    __shared__ float As[16 * APITCH];   // [k][m]
    __shared__ float Bs[128 * 20];      // [n][k]
    const int bn = blockIdx.x * 128, bm = blockIdx.y * 128;
    const int tid = threadIdx.x;
    const int warp = tid >> 5, lane = tid & 31;
    const int wm = warp >> 2, wn = warp & 3;     // warp tile: m64 x n32
    const int gq = lane >> 2, lt = lane & 3;
    const int r_ = tid >> 1, kq_ = (tid & 1) * 8;
    const bool vec = (K & 3) == 0;

    float acc[4][4][4] = {};
    for (int kbase = 0; kbase < K; kbase += 16) {
        // fill As
        {
            int gm = bm + r_;
            const float* ap = A + (size_t)gm * K + kbase + kq_;
            #pragma unroll
            for (int q = 0; q < 2; q++) {
                int gk = kbase + kq_ + q * 4;
                float4 v = make_float4(0.f, 0.f, 0.f, 0.f);
                if (gm < M) {
                    if (vec) { if (gk < K) v = *(const float4*)(ap + q * 4); }
                    else {
                        if (gk + 0 < K) v.x = ap[q * 4 + 0];
                        if (gk + 1 < K) v.y = ap[q * 4 + 1];
                        if (gk + 2 < K) v.z = ap[q * 4 + 2];
                        if (gk + 3 < K) v.w = ap[q * 4 + 3];
                    }
                }
                int kk = kq_ + q * 4;
                As[(kk + 0) * APITCH + r_] = f2tf(v.x);
                As[(kk + 1) * APITCH + r_] = f2tf(v.y);
                As[(kk + 2) * APITCH + r_] = f2tf(v.z);
                As[(kk + 3) * APITCH + r_] = f2tf(v.w);
            }
        }
        // fill Bs
        {
            int gn = bn + r_;
            const float* wp = W + (size_t)gn * K + kbase + kq_;
            #pragma unroll
            for (int q = 0; q < 2; q++) {
                int gk = kbase + kq_ + q * 4;
                float4 v = make_float4(0.f, 0.f, 0.f, 0.f);
                if (gn < N) {
                    if (vec) { if (gk < K) v = *(const float4*)(wp + q * 4); }
                    else {
                        if (gk + 0 < K) v.x = wp[q * 4 + 0];
                        if (gk + 1 < K) v.y = wp[q * 4 + 1];
                        if (gk + 2 < K) v.z = wp[q * 4 + 2];
                        if (gk + 3 < K) v.w = wp[q * 4 + 3];
                    }
                }
                int kk = kq_ + q * 4;
                Bs[r_ * 20 + kk + 0] = f2tf(v.x);
                Bs[r_ * 20 + kk + 1] = f2tf(v.y);
                Bs[r_ * 20 + kk + 2] = f2tf(v.z);
                Bs[r_ * 20 + kk + 3] = f2tf(v.w);
            }
        }
        __syncthreads();
        #pragma unroll
        for (int ks = 0; ks < 16; ks += 8) {
            unsigned a[4][4], b[4][2];
            #pragma unroll
            for (int mi = 0; mi < 4; mi++) {
                int row = wm * 64 + mi * 16 + gq;
                a[mi][0] = __float_as_uint(As[(ks + lt) * APITCH + row]);
                a[mi][1] = __float_as_uint(As[(ks + lt) * APITCH + row + 8]);
                a[mi][2] = __float_as_uint(As[(ks + lt + 4) * APITCH + row]);
                a[mi][3] = __float_as_uint(As[(ks + lt + 4) * APITCH + row + 8]);
            }
            #pragma unroll
            for (int ni = 0; ni < 4; ni++) {
                int nl = wn * 32 + ni * 8 + gq;
                b[ni][0] = __float_as_uint(Bs[nl * 20 + ks + lt]);
                b[ni][1] = __float_as_uint(Bs[nl * 20 + ks + lt + 4]);
            }
            #pragma unroll
            for (int mi = 0; mi < 4; mi++)
                #pragma unroll
                for (int ni = 0; ni < 4; ni++)
                    mma_tf32(acc[mi][ni], a[mi], b[ni]);
        }
        __syncthreads();
    }
    // ---- epilogue ----
    #pragma unroll
    for (int mi = 0; mi < 4; mi++) {
        #pragma unroll
        for (int ni = 0; ni < 4; ni++) {
            int gn = bn + wn * 32 + ni * 8 + 2 * lt;
            if (gn >= N) continue;
            #pragma unroll
            for (int half = 0; half < 2; half++) {
                int gm = bm + wm * 64 + mi * 16 + gq + half * 8;
                if (gm >= M) continue;
                float v0 = acc[mi][ni][half * 2 + 0] + bias[gn];
                float v1 = acc[mi][ni][half * 2 + 1] + bias[gn + 1];
                if (ACT == 1) { v0 = v0 > 0.f ? v0 : 0.1f * v0; v1 = v1 > 0.f ? v1 : 0.1f * v1; }
                else if (ACT == 2) { v0 = softplus_(v0) + 1e-4f; v1 = softplus_(v1) + 1e-4f; }
                *(float2*)&C[(size_t)gm * N + gn] = make_float2(v0, v1);
            }
        }
    }
}

// ---------------- latent scan ----------------
__global__ void k_latent(const float* __restrict__ hpost, const float* __restrict__ eps,
                         const float* __restrict__ zmW, const float* __restrict__ zmb,
                         const float* __restrict__ zsW, const float* __restrict__ zsb,
                         float* __restrict__ zg, float* __restrict__ zm, float* __restrict__ zs) {
    int b = blockIdx.x;
    __shared__ float red[6];
    __shared__ float zprev[ZZ];
    int tid = threadIdx.x;           // 192 = 6 warps
    int w = tid >> 5, lane = tid & 31;
    if (tid < ZZ) zprev[tid] = 0.f;
    __syncthreads();
    const float* Wrow = (w < 3) ? (zmW + (size_t)w * (HH + ZZ)) : (zsW + (size_t)(w - 3) * (HH + ZZ));
    for (int t = 0; t < TT; t++) {
        const float* hrow = hpost + ((size_t)b * TT + t) * HH;
        float s = 0.f;
        for (int k = lane; k < HH; k += 32) s += hrow[k] * Wrow[k];
        if (lane < ZZ) s += zprev[lane] * Wrow[HH + lane];
        #pragma unroll
        for (int o = 16; o; o >>= 1) s += __shfl_down_sync(0xffffffffu, s, o);
        if (lane == 0) red[w] = s;
        __syncthreads();
        if (tid < ZZ) {
            float mu = red[tid] + zmb[tid];
            float sd = softplus_(red[3 + tid] + zsb[tid]) + 1e-4f;
            size_t o = ((size_t)b * TT + t) * ZZ + tid;
            float zt = mu + sd * eps[o];
            zg[o] = zt; zm[o] = mu; zs[o] = sd;
            zprev[tid] = zt;
        }
        __syncthreads();
    }
}

// ---------------- planar flow stack ----------------
__global__ void k_flow(const float* __restrict__ zgen,
                       const float* __restrict__ fw, const float* __restrict__ fb,
                       const float* __restrict__ fu,
                       float* __restrict__ zfin, float* __restrict__ ldj) {
    __shared__ float s_uh[LL][ZZ], s_w[LL][ZZ], s_b[LL], s_uhw[LL];
    int tid = threadIdx.x;
    if (tid < LL) {
        float w0 = fw[tid * 3], w1 = fw[tid * 3 + 1], w2 = fw[tid * 3 + 2];
        float u0 = fu[tid * 3], u1 = fu[tid * 3 + 1], u2 = fu[tid * 3 + 2];
        float wu = w0 * u0 + w1 * u1 + w2 * u2;
        float m = -1.f + softplus_(wu);
        float c = (m - wu) / (w0 * w0 + w1 * w1 + w2 * w2 + 1e-7f);
        float uh0 = u0 + c * w0, uh1 = u1 + c * w1, uh2 = u2 + c * w2;
        s_uh[tid][0] = uh0; s_uh[tid][1] = uh1; s_uh[tid][2] = uh2;
        s_w[tid][0] = w0; s_w[tid][1] = w1; s_w[tid][2] = w2;
        s_b[tid] = fb[tid];
        s_uhw[tid] = uh0 * w0 + uh1 * w1 + uh2 * w2;
    }
    __syncthreads();
    int idx = blockIdx.x * blockDim.x + tid;
    if (idx >= BT) return;
    float z0 = zgen[idx * 3], z1 = zgen[idx * 3 + 1], z2 = zgen[idx * 3 + 2];
    float ld = 0.f;
    #pragma unroll
    for (int l = 0; l < LL; l++) {
        float lin = z0 * s_w[l][0] + z1 * s_w[l][1] + z2 * s_w[l][2] + s_b[l];
        float t = tanhf(lin);
        z0 += s_uh[l][0] * t; z1 += s_uh[l][1] * t; z2 += s_uh[l][2] * t;
        float det = 1.f + (1.f - t * t) * s_uhw[l];
        ld += logf(fabsf(det) + 1e-7f);
    }
    zfin[idx * 3] = z0; zfin[idx * 3 + 1] = z1; zfin[idx * 3 + 2] = z2;
    ldj[idx] = ld;
}

// ---------------- launch ----------------
extern "C" void kernel_launch(void* const* d_in, const int* in_sizes, int n_in,
                              void* d_out, int out_size) {
    const float* x       = (const float*)d_in[0];
    const float* eps     = (const float*)d_in[1];
    const float* enc_Wih = (const float*)d_in[2];
    const float* enc_Whh = (const float*)d_in[3];
    const float* enc_bih = (const float*)d_in[4];
    const float* enc_bhh = (const float*)d_in[5];
    const float* enc_W1  = (const float*)d_in[6];
    const float* enc_b1  = (const float*)d_in[7];
    const float* enc_W2  = (const float*)d_in[8];
    const float* enc_b2  = (const float*)d_in[9];
    const float* zm_W    = (const float*)d_in[10];
    const float* zm_b    = (const float*)d_in[11];
    const float* zs_W    = (const float*)d_in[12];
    const float* zs_b    = (const float*)d_in[13];
    const float* flow_w  = (const float*)d_in[14];
    const float* flow_b  = (const float*)d_in[15];
    const float* flow_u  = (const float*)d_in[16];
    const float* dec_Wih = (const float*)d_in[17];
    const float* dec_Whh = (const float*)d_in[18];
    const float* dec_bih = (const float*)d_in[19];
    const float* dec_bhh = (const float*)d_in[20];
    const float* dec_W1  = (const float*)d_in[21];
    const float* dec_b1  = (const float*)d_in[22];
    const float* dec_W2  = (const float*)d_in[23];
    const float* dec_b2  = (const float*)d_in[24];
    const float* xm_W    = (const float*)d_in[25];
    const float* xm_b    = (const float*)d_in[26];
    const float* xs_W    = (const float*)d_in[27];
    const float* xs_b    = (const float*)d_in[28];

    float *gi, *seq1, *seq2;
    cudaGetSymbolAddress((void**)&gi, g_gi);
    cudaGetSymbolAddress((void**)&seq1, g_seq1);
    cudaGetSymbolAddress((void**)&seq2, g_seq2);

    float* out  = (float*)d_out;
    float* o_mu = out;                              // [B,T,X]
    float* o_sd = o_mu + (size_t)BT * XX;           // [B,T,X]
    float* o_zg = o_sd + (size_t)BT * XX;           // [B,T,Z]
    float* o_zf = o_zg + (size_t)BT * ZZ;           // [B,T,Z]
    float* o_zm = o_zf + (size_t)BT * ZZ;           // [B,T,Z]
    float* o_zs = o_zm + (size_t)BT * ZZ;           // [B,T,Z]
    float* o_ld = o_zs + (size_t)BT * ZZ;           // [B,T,1]

    const int SMEMB = (CTILE * WPITCH + GRU_BK * APITCH + 128 * CPITCH) * 4;  // ~143 KB
    static bool attr_done = false;
    if (!attr_done) {
        cudaFuncSetAttribute(k_gru_tc<0>, cudaFuncAttributeMaxDynamicSharedMemorySize, SMEMB);
        cudaFuncSetAttribute(k_gru_tc<1>, cudaFuncAttributeMaxDynamicSharedMemorySize, SMEMB);
        attr_done = true;
    }

    const dim3 gGi((G3 + 127) / 128, (BT + 127) / 128);    // 12 x 400
    const dim3 gPost((HH + 127) / 128, (BT + 127) / 128);  // 4 x 400
    const dim3 gProj((XX + 127) / 128, (BT + 127) / 128);  // 1 x 400

    // ---- Encoder ----
    gemm_tc<0><<<gGi, 256>>>(x, enc_Wih, enc_bih, gi, BT, G3, XX);
    k_gru_tc<0><<<NBLK, 256, SMEMB>>>(gi, nullptr, nullptr, enc_Whh, enc_bhh, seq1);
    gemm_tc<1><<<gPost, 256>>>(seq1, enc_W1, enc_b1, seq2, BT, HH, HH);
    gemm_tc<1><<<gPost, 256>>>(seq2, enc_W2, enc_b2, seq1, BT, HH, HH);

    // ---- Latent scan + flows ----
    k_latent<<<BB, 192>>>(seq1, eps, zm_W, zm_b, zs_W, zs_b, o_zg, o_zm, o_zs);
    k_flow<<<(BT + 255) / 256, 256>>>(o_zg, flow_w, flow_b, flow_u, o_zf, o_ld);

    // ---- Decoder ----
    k_gru_tc<1><<<NBLK, 256, SMEMB>>>(o_zf, dec_Wih, dec_bih, dec_Whh, dec_bhh, seq2);
    gemm_tc<1><<<gPost, 256>>>(seq2, dec_W1, dec_b1, seq1, BT, HH, HH);
    gemm_tc<1><<<gPost, 256>>>(seq1, dec_W2, dec_b2, seq2, BT, HH, HH);

    // ---- Output projections ----
    gemm_tc<0><<<gProj, 256>>>(seq2, xm_W, xm_b, o_mu, BT, XX, HH);
    gemm_tc<2><<<gProj, 256>>>(seq2, xs_W, xs_b, o_sd, BT, XX, HH);
}

// round 6
// speedup vs baseline: 4.8199x; 1.0708x over previous
#include <cuda_runtime.h>
#include <math.h>

// ---------------- problem dims ----------------
#define BB  512
#define TT  100
#define XX  38
#define ZZ  3
#define HH  500
#define LL  20
#define G3  (3*HH)      // 1500
#define BT  (BB*TT)     // 51200

// ---- persistent GRU tiling (tensor core) ----
#define NBLK   128      // 4 M-tiles x 32 J-tiles
#define MTILE  128
#define JTILE  16
#define CTILE  48       // 3 gates * JTILE
#define WPITCH 516      // Ws k-pitch (516 mod 32 = 4 -> conflict-free frags)
#define GPITCH 36       // [col][k] pitch  (36 mod 32 = 4 -> conflict-free frags)
#define CPITCH 52
#define ABUF   (128*GPITCH)

// ---------------- scratch ----------------
__device__ float g_gi[(size_t)BT * G3];
__device__ float g_seq1[(size_t)BT * HH];
__device__ float g_seq2[(size_t)BT * HH];
__device__ float g_wtf[1038000];           // pre-tf32 weights
__device__ unsigned g_cnt = 0;
__device__ unsigned g_sense = 0;

// ---------------- helpers ----------------
__device__ __forceinline__ float sigm_(float x) { return 1.f / (1.f + expf(-x)); }
__device__ __forceinline__ float softplus_(float x) { return x > 15.f ? x : log1pf(expf(x)); }
__device__ __forceinline__ float f2tf(float f) {
    unsigned u; asm("cvt.rna.tf32.f32 %0, %1;" : "=r"(u) : "f"(f));
    return __uint_as_float(u);
}
__device__ __forceinline__ unsigned tfb(float f) {
    unsigned u; asm("cvt.rna.tf32.f32 %0, %1;" : "=r"(u) : "f"(f));
    return u;
}
__device__ __forceinline__ void mma_tf32(float* c, const unsigned* a, const unsigned* b) {
    asm volatile("mma.sync.aligned.m16n8k8.row.col.f32.tf32.tf32.f32 "
        "{%0,%1,%2,%3}, {%4,%5,%6,%7}, {%8,%9}, {%0,%1,%2,%3};\n"
        : "+f"(c[0]), "+f"(c[1]), "+f"(c[2]), "+f"(c[3])
        : "r"(a[0]), "r"(a[1]), "r"(a[2]), "r"(a[3]), "r"(b[0]), "r"(b[1]));
}
__device__ __forceinline__ unsigned smaddr(const void* p) {
    return (unsigned)__cvta_generic_to_shared(p);
}
__device__ __forceinline__ void cpasync16(unsigned dst, const void* src, int bytes) {
    asm volatile("cp.async.cg.shared.global [%0], [%1], 16, %2;"
                 :: "r"(dst), "l"(src), "r"(bytes));
}
__device__ __forceinline__ void cpcommit() { asm volatile("cp.async.commit_group;"); }
__device__ __forceinline__ void cpwait0()  { asm volatile("cp.async.wait_group 0;"); }

// ---------------- software grid barrier ----------------
__device__ __forceinline__ void gsync(unsigned gen, unsigned base) {
    __syncthreads();
    if (threadIdx.x == 0) {
        __threadfence();
        unsigned a = atomicAdd(&g_cnt, 1);
        if (a == NBLK - 1) {
            g_cnt = 0;
            __threadfence();
            *(volatile unsigned*)&g_sense = base + gen;
        } else {
            while ((unsigned)(*(volatile unsigned*)&g_sense - base) < gen) {}
        }
        __threadfence();
    }
    __syncthreads();
}

// ---------------- tf32 cvt fill ----------------
__global__ void k_cvt(const float* __restrict__ s, float* __restrict__ d, int n) {
    int i = blockIdx.x * blockDim.x + threadIdx.x;
    if (i < n) d[i] = f2tf(s[i]);
}

// ---------------- persistent GRU (tf32 mma, weight-stationary, cp.async pipeline) ----------------
template<int DEC>
__global__ void __launch_bounds__(256, 1)
k_gru_tc(const float* __restrict__ giz,
         const float* __restrict__ Wih, const float* __restrict__ bih,
         const float* __restrict__ Whh, const float* __restrict__ bhh,
         float* __restrict__ seq) {
    extern __shared__ float sm[];
    float* Ws = sm;                      // [CTILE][WPITCH]
    float* As = Ws + CTILE * WPITCH;     // [2][128][GPITCH]  (row-major [m][k])
    float* Cs = As + 2 * ABUF;           // [128][CPITCH]

    const int blk = blockIdx.x;
    const int mt = blk >> 5, jt = blk & 31;
    const int bm = mt * MTILE;
    const int jbase = jt * JTILE;
    const int tid = threadIdx.x;
    const int warp = tid >> 5, lane = tid & 31;
    const int wm = warp >> 1, wn = warp & 1;   // warp tile m32 x n24
    const int gq = lane >> 2, lt = lane & 3;
    const unsigned as_u = smaddr(As);

    // ---- load Whh slice (tf32) into Ws[c][k] ----
    for (int i = tid; i < CTILE * 512; i += 256) {
        int c = i >> 9, k = i & 511;
        int gate = c >> 4, jj = c & 15;
        int j = jbase + jj;
        float v = 0.f;
        if (j < HH && k < HH) v = f2tf(Whh[(size_t)(gate * HH + j) * HH + k]);
        Ws[c * WPITCH + k] = v;
    }
    __syncthreads();

    unsigned base = *(volatile unsigned*)&g_sense;

    for (int t = 0; t < TT; t++) {
        float acc[2][3][4] = {};
        if (t > 0) {
            // copy chunk c of h(t-1) into buffer buf
            auto docopy = [&](int c, int buf) {
                int kbase = c * 32;
                #pragma unroll
                for (int i = 0; i < 4; i++) {
                    int idx = tid + i * 256;
                    int row = idx >> 3, ch = idx & 7;
                    int gk = kbase + ch * 4;
                    const float* src = seq + ((size_t)(bm + row) * TT + (t - 1)) * HH + gk;
                    unsigned dst = as_u + (unsigned)((buf * ABUF + row * GPITCH + ch * 4) * 4);
                    cpasync16(dst, src, (gk < HH) ? 16 : 0);
                }
                cpcommit();
            };
            docopy(0, 0);
            for (int c = 0; c < 16; c++) {
                cpwait0();
                __syncthreads();
                if (c < 15) docopy(c + 1, (c + 1) & 1);
                const float* Ab = As + (c & 1) * ABUF;
                #pragma unroll
                for (int ks = 0; ks < 32; ks += 8) {
                    unsigned a[2][4], b[3][2];
                    #pragma unroll
                    for (int mi = 0; mi < 2; mi++) {
                        int row = wm * 32 + mi * 16 + gq;
                        a[mi][0] = tfb(Ab[row * GPITCH + ks + lt]);
                        a[mi][1] = tfb(Ab[(row + 8) * GPITCH + ks + lt]);
                        a[mi][2] = tfb(Ab[row * GPITCH + ks + lt + 4]);
                        a[mi][3] = tfb(Ab[(row + 8) * GPITCH + ks + lt + 4]);
                    }
                    int kg = c * 32 + ks;
                    #pragma unroll
                    for (int ni = 0; ni < 3; ni++) {
                        int cc = wn * 24 + ni * 8 + gq;
                        b[ni][0] = __float_as_uint(Ws[cc * WPITCH + kg + lt]);
                        b[ni][1] = __float_as_uint(Ws[cc * WPITCH + kg + lt + 4]);
                    }
                    #pragma unroll
                    for (int mi = 0; mi < 2; mi++)
                        #pragma unroll
                        for (int ni = 0; ni < 3; ni++)
                            mma_tf32(acc[mi][ni], a[mi], b[ni]);
                }
            }
            __syncthreads();
        }
        // ---- stash hidden-gate tile to Cs ----
        #pragma unroll
        for (int mi = 0; mi < 2; mi++)
            #pragma unroll
            for (int ni = 0; ni < 3; ni++) {
                int r0 = wm * 32 + mi * 16 + gq;
                int c0 = wn * 24 + ni * 8 + 2 * lt;
                *(float2*)&Cs[r0 * CPITCH + c0] = make_float2(acc[mi][ni][0], acc[mi][ni][1]);
                *(float2*)&Cs[(r0 + 8) * CPITCH + c0] = make_float2(acc[mi][ni][2], acc[mi][ni][3]);
            }
        __syncthreads();
        // ---- gate phase ----
        for (int u = tid; u < MTILE * JTILE; u += 256) {
            int m = u >> 4, jj = u & 15;
            int j = jbase + jj;
            if (j < HH) {
                int b = bm + m;
                float ghr = Cs[m * CPITCH + jj]      + bhh[j];
                float ghz = Cs[m * CPITCH + 16 + jj] + bhh[HH + j];
                float ghn = Cs[m * CPITCH + 32 + jj] + bhh[2 * HH + j];
                float gir, gzv, gin;
                if (DEC) {
                    const float* zb = giz + ((size_t)b * TT + t) * ZZ;
                    float z0 = zb[0], z1 = zb[1], z2 = zb[2];
                    int jr = j, jz = HH + j, jn = 2 * HH + j;
                    gir = bih[jr] + Wih[3*jr]*z0 + Wih[3*jr+1]*z1 + Wih[3*jr+2]*z2;
                    gzv = bih[jz] + Wih[3*jz]*z0 + Wih[3*jz+1]*z1 + Wih[3*jz+2]*z2;
                    gin = bih[jn] + Wih[3*jn]*z0 + Wih[3*jn+1]*z1 + Wih[3*jn+2]*z2;
                } else {
                    const float* gb = giz + ((size_t)b * TT + t) * G3;
                    gir = gb[j]; gzv = gb[HH + j]; gin = gb[2 * HH + j];
                }
                float r  = sigm_(gir + ghr);
                float zg = sigm_(gzv + ghz);
                float n  = tanhf(gin + r * ghn);
                float hpv = (t == 0) ? 0.f : seq[((size_t)b * TT + (t - 1)) * HH + j];
                seq[((size_t)b * TT + t) * HH + j] = (1.f - zg) * n + zg * hpv;
            }
        }
        gsync(t + 1, base);
    }
}

// ---------------- pipelined tf32 GEMM: C = act(A[M,K] @ W[N,K]^T + bias) ----------------
// Requirements: M % 128 == 0, K % 4 == 0 (K=500 here), W pre-tf32-rounded. N arbitrary even.
template<int ACT>
__global__ void __launch_bounds__(256, 2)
gemm_tc2(const float* __restrict__ A, const float* __restrict__ W,
         const float* __restrict__ bias, float* __restrict__ C,
         int M, int N, int K) {
    extern __shared__ float dsm[];
    float* As = dsm;              // [2][128][GPITCH]
    float* Bs = dsm + 2 * ABUF;   // [2][128][GPITCH]
    const int bn = blockIdx.x * 128, bm = blockIdx.y * 128;
    const int tid = threadIdx.x;
    const int warp = tid >> 5, lane = tid & 31;
    const int wm = warp >> 2, wn = warp & 3;   // warp tile m64 x n32
    const int gq = lane >> 2, lt = lane & 3;
    const unsigned as_u = smaddr(As), bs_u = smaddr(Bs);
    const int nt = (K + 31) / 32;

    auto docopy = [&](int c, int buf) {
        int kbase = c * 32;
        #pragma unroll
        for (int i = 0; i < 4; i++) {
            int idx = tid + i * 256;
            int row = idx >> 3, ch = idx & 7;
            int gk = kbase + ch * 4;
            unsigned off = (unsigned)((buf * ABUF + row * GPITCH + ch * 4) * 4);
            cpasync16(as_u + off, A + (size_t)(bm + row) * K + gk, (gk < K) ? 16 : 0);
            int gn = bn + row;
            cpasync16(bs_u + off, W + (size_t)gn * K + gk, (gn < N && gk < K) ? 16 : 0);
        }
        cpcommit();
    };

    float acc[4][4][4] = {};
    docopy(0, 0);
    for (int c = 0; c < nt; c++) {
        cpwait0();
        __syncthreads();
        if (c + 1 < nt) docopy(c + 1, (c + 1) & 1);
        const float* Ab = As + (c & 1) * ABUF;
        const float* Bb = Bs + (c & 1) * ABUF;
        #pragma unroll
        for (int ks = 0; ks < 32; ks += 8) {
            unsigned a[4][4], b[4][2];
            #pragma unroll
            for (int mi = 0; mi < 4; mi++) {
                int row = wm * 64 + mi * 16 + gq;
                a[mi][0] = tfb(Ab[row * GPITCH + ks + lt]);
                a[mi][1] = tfb(Ab[(row + 8) * GPITCH + ks + lt]);
                a[mi][2] = tfb(Ab[row * GPITCH + ks + lt + 4]);
                a[mi][3] = tfb(Ab[(row + 8) * GPITCH + ks + lt + 4]);
            }
            #pragma unroll
            for (int ni = 0; ni < 4; ni++) {
                int nl = wn * 32 + ni * 8 + gq;
                b[ni][0] = __float_as_uint(Bb[nl * GPITCH + ks + lt]);
                b[ni][1] = __float_as_uint(Bb[nl * GPITCH + ks + lt + 4]);
            }
            #pragma unroll
            for (int mi = 0; mi < 4; mi++)
                #pragma unroll
                for (int ni = 0; ni < 4; ni++)
                    mma_tf32(acc[mi][ni], a[mi], b[ni]);
        }
    }
    // ---- epilogue ----
    #pragma unroll
    for (int mi = 0; mi < 4; mi++) {
        #pragma unroll
        for (int ni = 0; ni < 4; ni++) {
            int gn = bn + wn * 32 + ni * 8 + 2 * lt;
            if (gn >= N) continue;
            #pragma unroll
            for (int half = 0; half < 2; half++) {
                int gm = bm + wm * 64 + mi * 16 + gq + half * 8;
                float v0 = acc[mi][ni][half * 2 + 0] + bias[gn];
                float v1 = acc[mi][ni][half * 2 + 1] + bias[gn + 1];
                if (ACT == 1) { v0 = v0 > 0.f ? v0 : 0.1f * v0; v1 = v1 > 0.f ? v1 : 0.1f * v1; }
                else if (ACT == 2) { v0 = softplus_(v0) + 1e-4f; v1 = softplus_(v1) + 1e-4f; }
                *(float2*)&C[(size_t)gm * N + gn] = make_float2(v0, v1);
            }
        }
    }
}

// ---------------- generic tf32 GEMM (K=38 gi path; R3 version) ----------------
#define APITCH 136
template<int ACT>
__global__ void __launch_bounds__(256, 1)
gemm_tc(const float* __restrict__ A, const float* __restrict__ W,
        const float* __restrict__ bias, float* __restrict__ C,
        int M, int N, int K) {
    __shared__ float As[16 * APITCH];
    __shared__ float Bs[128 * 20];
    const int bn = blockIdx.x * 128, bm = blockIdx.y * 128;
    const int tid = threadIdx.x;
    const int warp = tid >> 5, lane = tid & 31;
    const int wm = warp >> 2, wn = warp & 3;
    const int gq = lane >> 2, lt = lane & 3;
    const int r_ = tid >> 1, kq_ = (tid & 1) * 8;

    float acc[4][4][4] = {};
    for (int kbase = 0; kbase < K; kbase += 16) {
        {
            int gm = bm + r_;
            const float* ap = A + (size_t)gm * K + kbase + kq_;
            #pragma unroll
            for (int q = 0; q < 2; q++) {
                int gk = kbase + kq_ + q * 4;
                float4 v = make_float4(0.f, 0.f, 0.f, 0.f);
                if (gm < M) {
                    if (gk + 0 < K) v.x = ap[q * 4 + 0];
                    if (gk + 1 < K) v.y = ap[q * 4 + 1];
                    if (gk + 2 < K) v.z = ap[q * 4 + 2];
                    if (gk + 3 < K) v.w = ap[q * 4 + 3];
                }
                int kk = kq_ + q * 4;
                As[(kk + 0) * APITCH + r_] = f2tf(v.x);
                As[(kk + 1) * APITCH + r_] = f2tf(v.y);
                As[(kk + 2) * APITCH + r_] = f2tf(v.z);
                As[(kk + 3) * APITCH + r_] = f2tf(v.w);
            }
        }
        {
            int gn = bn + r_;
            const float* wp = W + (size_t)gn * K + kbase + kq_;
            #pragma unroll
            for (int q = 0; q < 2; q++) {
                int gk = kbase + kq_ + q * 4;
                float4 v = make_float4(0.f, 0.f, 0.f, 0.f);
                if (gn < N) {
                    if (gk + 0 < K) v.x = wp[q * 4 + 0];
                    if (gk + 1 < K) v.y = wp[q * 4 + 1];
                    if (gk + 2 < K) v.z = wp[q * 4 + 2];
                    if (gk + 3 < K) v.w = wp[q * 4 + 3];
                }
                int kk = kq_ + q * 4;
                Bs[r_ * 20 + kk + 0] = f2tf(v.x);
                Bs[r_ * 20 + kk + 1] = f2tf(v.y);
                Bs[r_ * 20 + kk + 2] = f2tf(v.z);
                Bs[r_ * 20 + kk + 3] = f2tf(v.w);
            }
        }
        __syncthreads();
        #pragma unroll
        for (int ks = 0; ks < 16; ks += 8) {
            unsigned a[4][4], b[4][2];
            #pragma unroll
            for (int mi = 0; mi < 4; mi++) {
                int row = wm * 64 + mi * 16 + gq;
                a[mi][0] = __float_as_uint(As[(ks + lt) * APITCH + row]);
                a[mi][1] = __float_as_uint(As[(ks + lt) * APITCH + row + 8]);
                a[mi][2] = __float_as_uint(As[(ks + lt + 4) * APITCH + row]);
                a[mi][3] = __float_as_uint(As[(ks + lt + 4) * APITCH + row + 8]);
            }
            #pragma unroll
            for (int ni = 0; ni < 4; ni++) {
                int nl = wn * 32 + ni * 8 + gq;
                b[ni][0] = __float_as_uint(Bs[nl * 20 + ks + lt]);
                b[ni][1] = __float_as_uint(Bs[nl * 20 + ks + lt + 4]);
            }
            #pragma unroll
            for (int mi = 0; mi < 4; mi++)
                #pragma unroll
                for (int ni = 0; ni < 4; ni++)
                    mma_tf32(acc[mi][ni], a[mi], b[ni]);
        }
        __syncthreads();
    }
    #pragma unroll
    for (int mi = 0; mi < 4; mi++) {
        #pragma unroll
        for (int ni = 0; ni < 4; ni++) {
            int gn = bn + wn * 32 + ni * 8 + 2 * lt;
            if (gn >= N) continue;
            #pragma unroll
            for (int half = 0; half < 2; half++) {
                int gm = bm + wm * 64 + mi * 16 + gq + half * 8;
                if (gm >= M) continue;
                float v0 = acc[mi][ni][half * 2 + 0] + bias[gn];
                float v1 = acc[mi][ni][half * 2 + 1] + bias[gn + 1];
                if (ACT == 1) { v0 = v0 > 0.f ? v0 : 0.1f * v0; v1 = v1 > 0.f ? v1 : 0.1f * v1; }
                else if (ACT == 2) { v0 = softplus_(v0) + 1e-4f; v1 = softplus_(v1) + 1e-4f; }
                *(float2*)&C[(size_t)gm * N + gn] = make_float2(v0, v1);
            }
        }
    }
}

// ---------------- latent scan ----------------
__global__ void k_latent(const float* __restrict__ hpost, const float* __restrict__ eps,
                         const float* __restrict__ zmW, const float* __restrict__ zmb,
                         const float* __restrict__ zsW, const float* __restrict__ zsb,
                         float* __restrict__ zg, float* __restrict__ zm, float* __restrict__ zs) {
    int b = blockIdx.x;
    __shared__ float red[6];
    __shared__ float zprev[ZZ];
    int tid = threadIdx.x;
    int w = tid >> 5, lane = tid & 31;
    if (tid < ZZ) zprev[tid] = 0.f;
    __syncthreads();
    const float* Wrow = (w < 3) ? (zmW + (size_t)w * (HH + ZZ)) : (zsW + (size_t)(w - 3) * (HH + ZZ));
    for (int t = 0; t < TT; t++) {
        const float* hrow = hpost + ((size_t)b * TT + t) * HH;
        float s = 0.f;
        for (int k = lane; k < HH; k += 32) s += hrow[k] * Wrow[k];
        if (lane < ZZ) s += zprev[lane] * Wrow[HH + lane];
        #pragma unroll
        for (int o = 16; o; o >>= 1) s += __shfl_down_sync(0xffffffffu, s, o);
        if (lane == 0) red[w] = s;
        __syncthreads();
        if (tid < ZZ) {
            float mu = red[tid] + zmb[tid];
            float sd = softplus_(red[3 + tid] + zsb[tid]) + 1e-4f;
            size_t o = ((size_t)b * TT + t) * ZZ + tid;
            float zt = mu + sd * eps[o];
            zg[o] = zt; zm[o] = mu; zs[o] = sd;
            zprev[tid] = zt;
        }
        __syncthreads();
    }
}

// ---------------- planar flow stack ----------------
__global__ void k_flow(const float* __restrict__ zgen,
                       const float* __restrict__ fw, const float* __restrict__ fb,
                       const float* __restrict__ fu,
                       float* __restrict__ zfin, float* __restrict__ ldj) {
    __shared__ float s_uh[LL][ZZ], s_w[LL][ZZ], s_b[LL], s_uhw[LL];
    int tid = threadIdx.x;
    if (tid < LL) {
        float w0 = fw[tid * 3], w1 = fw[tid * 3 + 1], w2 = fw[tid * 3 + 2];
        float u0 = fu[tid * 3], u1 = fu[tid * 3 + 1], u2 = fu[tid * 3 + 2];
        float wu = w0 * u0 + w1 * u1 + w2 * u2;
        float m = -1.f + softplus_(wu);
        float c = (m - wu) / (w0 * w0 + w1 * w1 + w2 * w2 + 1e-7f);
        float uh0 = u0 + c * w0, uh1 = u1 + c * w1, uh2 = u2 + c * w2;
        s_uh[tid][0] = uh0; s_uh[tid][1] = uh1; s_uh[tid][2] = uh2;
        s_w[tid][0] = w0; s_w[tid][1] = w1; s_w[tid][2] = w2;
        s_b[tid] = fb[tid];
        s_uhw[tid] = uh0 * w0 + uh1 * w1 + uh2 * w2;
    }
    __syncthreads();
    int idx = blockIdx.x * blockDim.x + tid;
    if (idx >= BT) return;
    float z0 = zgen[idx * 3], z1 = zgen[idx * 3 + 1], z2 = zgen[idx * 3 + 2];
    float ld = 0.f;
    #pragma unroll
    for (int l = 0; l < LL; l++) {
        float lin = z0 * s_w[l][0] + z1 * s_w[l][1] + z2 * s_w[l][2] + s_b[l];
        float t = tanhf(lin);
        z0 += s_uh[l][0] * t; z1 += s_uh[l][1] * t; z2 += s_uh[l][2] * t;
        float det = 1.f + (1.f - t * t) * s_uhw[l];
        ld += logf(fabsf(det) + 1e-7f);
    }
    zfin[idx * 3] = z0; zfin[idx * 3 + 1] = z1; zfin[idx * 3 + 2] = z2;
    ldj[idx] = ld;
}

// ---------------- launch ----------------
extern "C" void kernel_launch(void* const* d_in, const int* in_sizes, int n_in,
                              void* d_out, int out_size) {
    const float* x       = (const float*)d_in[0];
    const float* eps     = (const float*)d_in[1];
    const float* enc_Wih = (const float*)d_in[2];
    const float* enc_Whh = (const float*)d_in[3];
    const float* enc_bih = (const float*)d_in[4];
    const float* enc_bhh = (const float*)d_in[5];
    const float* enc_W1  = (const float*)d_in[6];
    const float* enc_b1  = (const float*)d_in[7];
    const float* enc_W2  = (const float*)d_in[8];
    const float* enc_b2  = (const float*)d_in[9];
    const float* zm_W    = (const float*)d_in[10];
    const float* zm_b    = (const float*)d_in[11];
    const float* zs_W    = (const float*)d_in[12];
    const float* zs_b    = (const float*)d_in[13];
    const float* flow_w  = (const float*)d_in[14];
    const float* flow_b  = (const float*)d_in[15];
    const float* flow_u  = (const float*)d_in[16];
    const float* dec_Wih = (const float*)d_in[17];
    const float* dec_Whh = (const float*)d_in[18];
    const float* dec_bih = (const float*)d_in[19];
    const float* dec_bhh = (const float*)d_in[20];
    const float* dec_W1  = (const float*)d_in[21];
    const float* dec_b1  = (const float*)d_in[22];
    const float* dec_W2  = (const float*)d_in[23];
    const float* dec_b2  = (const float*)d_in[24];
    const float* xm_W    = (const float*)d_in[25];
    const float* xm_b    = (const float*)d_in[26];
    const float* xs_W    = (const float*)d_in[27];
    const float* xs_b    = (const float*)d_in[28];

    float *gi, *seq1, *seq2, *wtf;
    cudaGetSymbolAddress((void**)&gi, g_gi);
    cudaGetSymbolAddress((void**)&seq1, g_seq1);
    cudaGetSymbolAddress((void**)&seq2, g_seq2);
    cudaGetSymbolAddress((void**)&wtf, g_wtf);
    float* wW1e = wtf + 0;
    float* wW2e = wtf + 250000;
    float* wW1d = wtf + 500000;
    float* wW2d = wtf + 750000;
    float* wXm  = wtf + 1000000;
    float* wXs  = wtf + 1019000;

    float* out  = (float*)d_out;
    float* o_mu = out;
    float* o_sd = o_mu + (size_t)BT * XX;
    float* o_zg = o_sd + (size_t)BT * XX;
    float* o_zf = o_zg + (size_t)BT * ZZ;
    float* o_zm = o_zf + (size_t)BT * ZZ;
    float* o_zs = o_zm + (size_t)BT * ZZ;
    float* o_ld = o_zs + (size_t)BT * ZZ;

    const int GRUSM = (CTILE * WPITCH + 2 * ABUF + 128 * CPITCH) * 4;  // ~188 KB? -> check: 24768+9216+6656 = 40640*4 = 162,560 B
    const int GEMSM = 4 * ABUF * 4;                                    // 73,728 B
    static bool attr_done = false;
    if (!attr_done) {
        cudaFuncSetAttribute(k_gru_tc<0>, cudaFuncAttributeMaxDynamicSharedMemorySize, GRUSM);
        cudaFuncSetAttribute(k_gru_tc<1>, cudaFuncAttributeMaxDynamicSharedMemorySize, GRUSM);
        cudaFuncSetAttribute(gemm_tc2<0>, cudaFuncAttributeMaxDynamicSharedMemorySize, GEMSM);
        cudaFuncSetAttribute(gemm_tc2<1>, cudaFuncAttributeMaxDynamicSharedMemorySize, GEMSM);
        cudaFuncSetAttribute(gemm_tc2<2>, cudaFuncAttributeMaxDynamicSharedMemorySize, GEMSM);
        attr_done = true;
    }

    // ---- pre-convert K=500 weights to tf32 ----
    k_cvt<<<(250000 + 255) / 256, 256>>>(enc_W1, wW1e, 250000);
    k_cvt<<<(250000 + 255) / 256, 256>>>(enc_W2, wW2e, 250000);
    k_cvt<<<(250000 + 255) / 256, 256>>>(dec_W1, wW1d, 250000);
    k_cvt<<<(250000 + 255) / 256, 256>>>(dec_W2, wW2d, 250000);
    k_cvt<<<(19000 + 255) / 256, 256>>>(xm_W, wXm, 19000);
    k_cvt<<<(19000 + 255) / 256, 256>>>(xs_W, wXs, 19000);

    const dim3 gGi((G3 + 127) / 128, (BT + 127) / 128);    // 12 x 400
    const dim3 gPost((HH + 127) / 128, (BT + 127) / 128);  // 4 x 400
    const dim3 gProj(1, BT / 128);                         // 1 x 400

    // ---- Encoder ----
    gemm_tc<0><<<gGi, 256>>>(x, enc_Wih, enc_bih, gi, BT, G3, XX);
    k_gru_tc<0><<<NBLK, 256, GRUSM>>>(gi, nullptr, nullptr, enc_Whh, enc_bhh, seq1);
    gemm_tc2<1><<<gPost, 256, GEMSM>>>(seq1, wW1e, enc_b1, seq2, BT, HH, HH);
    gemm_tc2<1><<<gPost, 256, GEMSM>>>(seq2, wW2e, enc_b2, seq1, BT, HH, HH);

    // ---- Latent scan + flows ----
    k_latent<<<BB, 192>>>(seq1, eps, zm_W, zm_b, zs_W, zs_b, o_zg, o_zm, o_zs);
    k_flow<<<(BT + 255) / 256, 256>>>(o_zg, flow_w, flow_b, flow_u, o_zf, o_ld);

    // ---- Decoder ----
    k_gru_tc<1><<<NBLK, 256, GRUSM>>>(o_zf, dec_Wih, dec_bih, dec_Whh, dec_bhh, seq2);
    gemm_tc2<1><<<gPost, 256, GEMSM>>>(seq2, wW1d, dec_b1, seq1, BT, HH, HH);
    gemm_tc2<1><<<gPost, 256, GEMSM>>>(seq1, wW2d, dec_b2, seq2, BT, HH, HH);

    // ---- Output projections ----
    gemm_tc2<0><<<gProj, 256, GEMSM>>>(seq2, wXm, xm_b, o_mu, BT, XX, HH);
    gemm_tc2<2><<<gProj, 256, GEMSM>>>(seq2, wXs, xs_b, o_sd, BT, XX, HH);
}

// round 9
// speedup vs baseline: 8.0445x; 1.6690x over previous
#include <cuda_runtime.h>
#include <math.h>

// ---------------- problem dims ----------------
#define BB  512
#define TT  100
#define XX  38
#define ZZ  3
#define HH  500
#define LL  20
#define G3  (3*HH)      // 1500
#define BT  (BB*TT)     // 51200

// ---- persistent GRU tiling ----
#define NBLK   128      // 4 m-groups x 32 j-tiles
#define MTILE  128
#define JTILE  16
#define CTILE  48       // 3 gates * JTILE
#define WPITCH 516      // Ws k-pitch (mod 32 = 4 -> conflict-free)
#define AP2    68       // GRU A pitch (mod 32 = 4)
#define GCH    64       // GRU k-chunk
#define ABUF2  (128*AP2)
#define CPITCH 52
// smem float offsets
#define OFF_WS  0
#define OFF_AS  (OFF_WS + CTILE*WPITCH)        // 24768
#define OFF_CS  (OFF_AS + 2*ABUF2)             // 42176
#define OFF_HS  (OFF_CS + 128*CPITCH)          // 48832
#define OFF_ZT  (OFF_HS + 128*JTILE)           // 50880
#define OFF_WI  (OFF_ZT + 384)                 // 51264
#define OFF_BI  (OFF_WI + CTILE*3)             // 51408
#define OFF_BH  (OFF_BI + CTILE)               // 51456
#define GRU_FLOATS (OFF_BH + CTILE)            // 51504 -> 206,016 B

// ---- pipelined GEMM tiling ----
#define GPITCH 36
#define ABUF   (128*GPITCH)

// ---------------- scratch ----------------
__device__ float g_gi[(size_t)BT * G3];
__device__ float g_seq1[(size_t)BT * HH];
__device__ float g_seq2[(size_t)BT * HH];
__device__ float g_wtf[1038000];
__device__ unsigned g_cnt4[128];    // per-m-group barrier counters (stride 32)
__device__ unsigned g_sense4[128];

// ---------------- helpers ----------------
__device__ __forceinline__ float sigm_(float x) { return 1.f / (1.f + expf(-x)); }
__device__ __forceinline__ float softplus_(float x) { return x > 15.f ? x : log1pf(expf(x)); }
__device__ __forceinline__ float f2tf(float f) {
    unsigned u; asm("cvt.rna.tf32.f32 %0, %1;" : "=r"(u) : "f"(f));
    return __uint_as_float(u);
}
__device__ __forceinline__ void mma_tf32(float* c, const unsigned* a, const unsigned* b) {
    asm volatile("mma.sync.aligned.m16n8k8.row.col.f32.tf32.tf32.f32 "
        "{%0,%1,%2,%3}, {%4,%5,%6,%7}, {%8,%9}, {%0,%1,%2,%3};\n"
        : "+f"(c[0]), "+f"(c[1]), "+f"(c[2]), "+f"(c[3])
        : "r"(a[0]), "r"(a[1]), "r"(a[2]), "r"(a[3]), "r"(b[0]), "r"(b[1]));
}
__device__ __forceinline__ unsigned smaddr(const void* p) {
    return (unsigned)__cvta_generic_to_shared(p);
}
__device__ __forceinline__ void cpasync16(unsigned dst, const void* src, int bytes) {
    asm volatile("cp.async.cg.shared.global [%0], [%1], 16, %2;"
                 :: "r"(dst), "l"(src), "r"(bytes));
}
__device__ __forceinline__ void cpcommit() { asm volatile("cp.async.commit_group;"); }
__device__ __forceinline__ void cpwait0()  { asm volatile("cp.async.wait_group 0;"); }

// ---------------- per-m-group barrier (32 CTAs each) ----------------
__device__ __forceinline__ void gsync_mt(int mt, unsigned gen, unsigned base) {
    __syncthreads();
    if (threadIdx.x == 0) {
        __threadfence();
        unsigned a = atomicAdd(&g_cnt4[mt * 32], 1);
        if (a == 31) {
            g_cnt4[mt * 32] = 0;
            __threadfence();
            *(volatile unsigned*)&g_sense4[mt * 32] = base + gen;
        } else {
            while ((unsigned)(*(volatile unsigned*)&g_sense4[mt * 32] - base) < gen) {}
        }
        __threadfence();
    }
    __syncthreads();
}

// ---------------- tf32 cvt fill ----------------
__global__ void k_cvt(const float* __restrict__ s, float* __restrict__ d, int n) {
    int i = blockIdx.x * blockDim.x + threadIdx.x;
    if (i < n) d[i] = f2tf(s[i]);
}

// ---------------- persistent GRU ----------------
// DEC=0: giz = input gates [B,T,3H] (incl bih). DEC=1: giz = z_fin [B,T,3].
template<int DEC>
__global__ void __launch_bounds__(256, 1)
k_gru_tc(const float* __restrict__ giz,
         const float* __restrict__ Wih, const float* __restrict__ bih,
         const float* __restrict__ Whh, const float* __restrict__ bhh,
         float* __restrict__ seq) {
    extern __shared__ float sm[];
    float* Ws  = sm + OFF_WS;
    float* As  = sm + OFF_AS;
    float* Cs  = sm + OFF_CS;
    float* Hs  = sm + OFF_HS;
    float* Zt  = sm + OFF_ZT;
    float* Wis = sm + OFF_WI;
    float* bis = sm + OFF_BI;
    float* bhs = sm + OFF_BH;

    const int blk = blockIdx.x;
    const int mt = blk >> 5, jt = blk & 31;
    const int bm = mt * MTILE;
    const int jbase = jt * JTILE;
    const int tid = threadIdx.x;
    const int warp = tid >> 5, lane = tid & 31;
    const int wm = warp >> 1, wn = warp & 1;   // warp tile m32 x n24
    const int gq = lane >> 2, lt = lane & 3;
    const unsigned as_u = smaddr(As);

    // ---- init: Whh slice (tf32), biases, dec Wih tile, zero Hs ----
    for (int i = tid; i < CTILE * 512; i += 256) {
        int c = i >> 9, k = i & 511;
        int gate = c >> 4, jj = c & 15;
        int j = jbase + jj;
        float v = 0.f;
        if (j < HH && k < HH) v = f2tf(Whh[(size_t)(gate * HH + j) * HH + k]);
        Ws[c * WPITCH + k] = v;
    }
    for (int i = tid; i < 128 * JTILE; i += 256) Hs[i] = 0.f;
    if (tid < CTILE) {
        int gate = tid >> 4, jj = tid & 15;
        int j = jbase + jj;
        int row = gate * HH + ((j < HH) ? j : 0);
        bhs[tid] = bhh[row];
        if (DEC) {
            bis[tid] = bih[row];
            Wis[tid * 3 + 0] = Wih[3 * row + 0];
            Wis[tid * 3 + 1] = Wih[3 * row + 1];
            Wis[tid * 3 + 2] = Wih[3 * row + 2];
        }
    }
    __syncthreads();

    unsigned base = *(volatile unsigned*)&g_sense4[mt * 32];

    for (int t = 0; t < TT; t++) {
        float acc[2][3][4] = {};
        if (t > 0) {
            auto docopy = [&](int c, int buf) {
                int kbase = c * GCH;
                #pragma unroll
                for (int i = 0; i < 8; i++) {
                    int idx = tid + i * 256;
                    int row = idx >> 4, ch = idx & 15;
                    int gk = kbase + ch * 4;
                    int gks = (gk < 496) ? gk : 496;
                    const float* src = seq + ((size_t)(bm + row) * TT + (t - 1)) * HH + gks;
                    unsigned dst = as_u + (unsigned)((buf * ABUF2 + row * AP2 + ch * 4) * 4);
                    cpasync16(dst, src, (gk < HH) ? 16 : 0);
                }
                cpcommit();
            };
            docopy(0, 0);
            for (int c = 0; c < 8; c++) {
                cpwait0();
                __syncthreads();
                if (c < 7) docopy(c + 1, (c + 1) & 1);
                const float* Ab = As + (c & 1) * ABUF2;
                #pragma unroll
                for (int ks = 0; ks < GCH; ks += 8) {
                    int kg = c * GCH + ks;
                    unsigned a[2][4], b[3][2];
                    #pragma unroll
                    for (int mi = 0; mi < 2; mi++) {
                        int row = wm * 32 + mi * 16 + gq;
                        a[mi][0] = __float_as_uint(Ab[row * AP2 + ks + lt]);
                        a[mi][1] = __float_as_uint(Ab[(row + 8) * AP2 + ks + lt]);
                        a[mi][2] = __float_as_uint(Ab[row * AP2 + ks + lt + 4]);
                        a[mi][3] = __float_as_uint(Ab[(row + 8) * AP2 + ks + lt + 4]);
                    }
                    #pragma unroll
                    for (int ni = 0; ni < 3; ni++) {
                        int cc = wn * 24 + ni * 8 + gq;
                        b[ni][0] = __float_as_uint(Ws[cc * WPITCH + kg + lt]);
                        b[ni][1] = __float_as_uint(Ws[cc * WPITCH + kg + lt + 4]);
                    }
                    #pragma unroll
                    for (int mi = 0; mi < 2; mi++)
                        #pragma unroll
                        for (int ni = 0; ni < 3; ni++)
                            mma_tf32(acc[mi][ni], a[mi], b[ni]);
                }
            }
            __syncthreads();
        }
        // ---- stash hidden-gate tile ----
        #pragma unroll
        for (int mi = 0; mi < 2; mi++)
            #pragma unroll
            for (int ni = 0; ni < 3; ni++) {
                int r0 = wm * 32 + mi * 16 + gq;
                int c0 = wn * 24 + ni * 8 + 2 * lt;
                *(float2*)&Cs[r0 * CPITCH + c0] = make_float2(acc[mi][ni][0], acc[mi][ni][1]);
                *(float2*)&Cs[(r0 + 8) * CPITCH + c0] = make_float2(acc[mi][ni][2], acc[mi][ni][3]);
            }
        if (DEC) {
            // FIX: 384 entries, 256 threads -> strided loop (R8 bug: only 256 written)
            for (int i = tid; i < MTILE * ZZ; i += 256)
                Zt[i] = giz[((size_t)(bm + (i / 3)) * TT + t) * ZZ + (i % 3)];
        }
        __syncthreads();
        // ---- gate phase ----
        for (int u = tid; u < MTILE * JTILE; u += 256) {
            int m = u >> 4, jj = u & 15;
            int j = jbase + jj;
            if (j < HH) {
                int b = bm + m;
                float ghr = Cs[m * CPITCH + jj]      + bhs[jj];
                float ghz = Cs[m * CPITCH + 16 + jj] + bhs[16 + jj];
                float ghn = Cs[m * CPITCH + 32 + jj] + bhs[32 + jj];
                float gir, gzv, gin;
                if (DEC) {
                    float z0 = Zt[m * 3], z1 = Zt[m * 3 + 1], z2 = Zt[m * 3 + 2];
                    gir = bis[jj]      + Wis[jj * 3] * z0           + Wis[jj * 3 + 1] * z1           + Wis[jj * 3 + 2] * z2;
                    gzv = bis[16 + jj] + Wis[(16 + jj) * 3] * z0    + Wis[(16 + jj) * 3 + 1] * z1    + Wis[(16 + jj) * 3 + 2] * z2;
                    gin = bis[32 + jj] + Wis[(32 + jj) * 3] * z0    + Wis[(32 + jj) * 3 + 1] * z1    + Wis[(32 + jj) * 3 + 2] * z2;
                } else {
                    const float* gb = giz + ((size_t)b * TT + t) * G3;
                    gir = gb[j]; gzv = gb[HH + j]; gin = gb[2 * HH + j];
                }
                float r  = sigm_(gir + ghr);
                float zg = sigm_(gzv + ghz);
                float n  = tanhf(gin + r * ghn);
                float hpv = Hs[u];
                float hn = f2tf((1.f - zg) * n + zg * hpv);
                Hs[u] = hn;
                seq[((size_t)b * TT + t) * HH + j] = hn;
            }
        }
        gsync_mt(mt, t + 1, base);
    }
}

// ---------------- pipelined tf32 GEMM: C = act(A @ W^T + bias) ----------------
// A and W must be pre-tf32-rounded. M%128==0, K%4==0. TFOUT: round output to tf32.
template<int ACT, int TFOUT>
__global__ void __launch_bounds__(256, 2)
gemm_tc2(const float* __restrict__ A, const float* __restrict__ W,
         const float* __restrict__ bias, float* __restrict__ C,
         int M, int N, int K) {
    extern __shared__ float dsm[];
    float* As = dsm;
    float* Bs = dsm + 2 * ABUF;
    const int bn = blockIdx.x * 128, bm = blockIdx.y * 128;
    const int tid = threadIdx.x;
    const int warp = tid >> 5, lane = tid & 31;
    const int wm = warp >> 2, wn = warp & 3;
    const int gq = lane >> 2, lt = lane & 3;
    const unsigned as_u = smaddr(As), bs_u = smaddr(Bs);
    const int nt = (K + 31) / 32;

    auto docopy = [&](int c, int buf) {
        int kbase = c * 32;
        #pragma unroll
        for (int i = 0; i < 4; i++) {
            int idx = tid + i * 256;
            int row = idx >> 3, ch = idx & 7;
            int gk = kbase + ch * 4;
            int gks = (gk < K) ? gk : 0;
            unsigned off = (unsigned)((buf * ABUF + row * GPITCH + ch * 4) * 4);
            cpasync16(as_u + off, A + (size_t)(bm + row) * K + gks, (gk < K) ? 16 : 0);
            int gn = bn + row;
            cpasync16(bs_u + off, W + (size_t)((gn < N) ? gn : 0) * K + gks, (gn < N && gk < K) ? 16 : 0);
        }
        cpcommit();
    };

    float acc[4][4][4] = {};
    docopy(0, 0);
    for (int c = 0; c < nt; c++) {
        cpwait0();
        __syncthreads();
        if (c + 1 < nt) docopy(c + 1, (c + 1) & 1);
        const float* Ab = As + (c & 1) * ABUF;
        const float* Bb = Bs + (c & 1) * ABUF;
        #pragma unroll
        for (int ks = 0; ks < 32; ks += 8) {
            unsigned a[4][4], b[4][2];
            #pragma unroll
            for (int mi = 0; mi < 4; mi++) {
                int row = wm * 64 + mi * 16 + gq;
                a[mi][0] = __float_as_uint(Ab[row * GPITCH + ks + lt]);
                a[mi][1] = __float_as_uint(Ab[(row + 8) * GPITCH + ks + lt]);
                a[mi][2] = __float_as_uint(Ab[row * GPITCH + ks + lt + 4]);
                a[mi][3] = __float_as_uint(Ab[(row + 8) * GPITCH + ks + lt + 4]);
            }
            #pragma unroll
            for (int ni = 0; ni < 4; ni++) {
                int nl = wn * 32 + ni * 8 + gq;
                b[ni][0] = __float_as_uint(Bb[nl * GPITCH + ks + lt]);
                b[ni][1] = __float_as_uint(Bb[nl * GPITCH + ks + lt + 4]);
            }
            #pragma unroll
            for (int mi = 0; mi < 4; mi++)
                #pragma unroll
                for (int ni = 0; ni < 4; ni++)
                    mma_tf32(acc[mi][ni], a[mi], b[ni]);
        }
    }
    #pragma unroll
    for (int mi = 0; mi < 4; mi++) {
        #pragma unroll
        for (int ni = 0; ni < 4; ni++) {
            int gn = bn + wn * 32 + ni * 8 + 2 * lt;
            if (gn >= N) continue;
            #pragma unroll
            for (int half = 0; half < 2; half++) {
                int gm = bm + wm * 64 + mi * 16 + gq + half * 8;
                float v0 = acc[mi][ni][half * 2 + 0] + bias[gn];
                float v1 = acc[mi][ni][half * 2 + 1] + bias[gn + 1];
                if (ACT == 1) { v0 = v0 > 0.f ? v0 : 0.1f * v0; v1 = v1 > 0.f ? v1 : 0.1f * v1; }
                else if (ACT == 2) { v0 = softplus_(v0) + 1e-4f; v1 = softplus_(v1) + 1e-4f; }
                if (TFOUT) { v0 = f2tf(v0); v1 = f2tf(v1); }
                *(float2*)&C[(size_t)gm * N + gn] = make_float2(v0, v1);
            }
        }
    }
}

// ---------------- generic tf32 GEMM (K=38 gi path) ----------------
#define APITCH 136
template<int ACT>
__global__ void __launch_bounds__(256, 1)
gemm_tc(const float* __restrict__ A, const float* __restrict__ W,
        const float* __restrict__ bias, float* __restrict__ C,
        int M, int N, int K) {
    __shared__ float As[16 * APITCH];
    __shared__ float Bs[128 * 20];
    const int bn = blockIdx.x * 128, bm = blockIdx.y * 128;
    const int tid = threadIdx.x;
    const int warp = tid >> 5, lane = tid & 31;
    const int wm = warp >> 2, wn = warp & 3;
    const int gq = lane >> 2, lt = lane & 3;
    const int r_ = tid >> 1, kq_ = (tid & 1) * 8;

    float acc[4][4][4] = {};
    for (int kbase = 0; kbase < K; kbase += 16) {
        {
            int gm = bm + r_;
            const float* ap = A + (size_t)gm * K + kbase + kq_;
            #pragma unroll
            for (int q = 0; q < 2; q++) {
                int gk = kbase + kq_ + q * 4;
                float4 v = make_float4(0.f, 0.f, 0.f, 0.f);
                if (gm < M) {
                    if (gk + 0 < K) v.x = ap[q * 4 + 0];
                    if (gk + 1 < K) v.y = ap[q * 4 + 1];
                    if (gk + 2 < K) v.z = ap[q * 4 + 2];
                    if (gk + 3 < K) v.w = ap[q * 4 + 3];
                }
                int kk = kq_ + q * 4;
                As[(kk + 0) * APITCH + r_] = f2tf(v.x);
                As[(kk + 1) * APITCH + r_] = f2tf(v.y);
                As[(kk + 2) * APITCH + r_] = f2tf(v.z);
                As[(kk + 3) * APITCH + r_] = f2tf(v.w);
            }
        }
        {
            int gn = bn + r_;
            const float* wp = W + (size_t)gn * K + kbase + kq_;
            #pragma unroll
            for (int q = 0; q < 2; q++) {
                int gk = kbase + kq_ + q * 4;
                float4 v = make_float4(0.f, 0.f, 0.f, 0.f);
                if (gn < N) {
                    if (gk + 0 < K) v.x = wp[q * 4 + 0];
                    if (gk + 1 < K) v.y = wp[q * 4 + 1];
                    if (gk + 2 < K) v.z = wp[q * 4 + 2];
                    if (gk + 3 < K) v.w = wp[q * 4 + 3];
                }
                int kk = kq_ + q * 4;
                Bs[r_ * 20 + kk + 0] = f2tf(v.x);
                Bs[r_ * 20 + kk + 1] = f2tf(v.y);
                Bs[r_ * 20 + kk + 2] = f2tf(v.z);
                Bs[r_ * 20 + kk + 3] = f2tf(v.w);
            }
        }
        __syncthreads();
        #pragma unroll
        for (int ks = 0; ks < 16; ks += 8) {
            unsigned a[4][4], b[4][2];
            #pragma unroll
            for (int mi = 0; mi < 4; mi++) {
                int row = wm * 64 + mi * 16 + gq;
                a[mi][0] = __float_as_uint(As[(ks + lt) * APITCH + row]);
                a[mi][1] = __float_as_uint(As[(ks + lt) * APITCH + row + 8]);
                a[mi][2] = __float_as_uint(As[(ks + lt + 4) * APITCH + row]);
                a[mi][3] = __float_as_uint(As[(ks + lt + 4) * APITCH + row + 8]);
            }
            #pragma unroll
            for (int ni = 0; ni < 4; ni++) {
                int nl = wn * 32 + ni * 8 + gq;
                b[ni][0] = __float_as_uint(Bs[nl * 20 + ks + lt]);
                b[ni][1] = __float_as_uint(Bs[nl * 20 + ks + lt + 4]);
            }
            #pragma unroll
            for (int mi = 0; mi < 4; mi++)
                #pragma unroll
                for (int ni = 0; ni < 4; ni++)
                    mma_tf32(acc[mi][ni], a[mi], b[ni]);
        }
        __syncthreads();
    }
    #pragma unroll
    for (int mi = 0; mi < 4; mi++) {
        #pragma unroll
        for (int ni = 0; ni < 4; ni++) {
            int gn = bn + wn * 32 + ni * 8 + 2 * lt;
            if (gn >= N) continue;
            #pragma unroll
            for (int half = 0; half < 2; half++) {
                int gm = bm + wm * 64 + mi * 16 + gq + half * 8;
                if (gm >= M) continue;
                float v0 = acc[mi][ni][half * 2 + 0] + bias[gn];
                float v1 = acc[mi][ni][half * 2 + 1] + bias[gn + 1];
                if (ACT == 1) { v0 = v0 > 0.f ? v0 : 0.1f * v0; v1 = v1 > 0.f ? v1 : 0.1f * v1; }
                else if (ACT == 2) { v0 = softplus_(v0) + 1e-4f; v1 = softplus_(v1) + 1e-4f; }
                *(float2*)&C[(size_t)gm * N + gn] = make_float2(v0, v1);
            }
        }
    }
}

// ---------------- latent scan ----------------
__global__ void k_latent(const float* __restrict__ hpost, const float* __restrict__ eps,
                         const float* __restrict__ zmW, const float* __restrict__ zmb,
                         const float* __restrict__ zsW, const float* __restrict__ zsb,
                         float* __restrict__ zg, float* __restrict__ zm, float* __restrict__ zs) {
    int b = blockIdx.x;
    __shared__ float red[6];
    __shared__ float zprev[ZZ];
    int tid = threadIdx.x;
    int w = tid >> 5, lane = tid & 31;
    if (tid < ZZ) zprev[tid] = 0.f;
    __syncthreads();
    const float* Wrow = (w < 3) ? (zmW + (size_t)w * (HH + ZZ)) : (zsW + (size_t)(w - 3) * (HH + ZZ));
    for (int t = 0; t < TT; t++) {
        const float* hrow = hpost + ((size_t)b * TT + t) * HH;
        float s = 0.f;
        for (int k = lane; k < HH; k += 32) s += hrow[k] * Wrow[k];
        if (lane < ZZ) s += zprev[lane] * Wrow[HH + lane];
        #pragma unroll
        for (int o = 16; o; o >>= 1) s += __shfl_down_sync(0xffffffffu, s, o);
        if (lane == 0) red[w] = s;
        __syncthreads();
        if (tid < ZZ) {
            float mu = red[tid] + zmb[tid];
            float sd = softplus_(red[3 + tid] + zsb[tid]) + 1e-4f;
            size_t o = ((size_t)b * TT + t) * ZZ + tid;
            float zt = mu + sd * eps[o];
            zg[o] = zt; zm[o] = mu; zs[o] = sd;
            zprev[tid] = zt;
        }
        __syncthreads();
    }
}

// ---------------- planar flow stack ----------------
__global__ void k_flow(const float* __restrict__ zgen,
                       const float* __restrict__ fw, const float* __restrict__ fb,
                       const float* __restrict__ fu,
                       float* __restrict__ zfin, float* __restrict__ ldj) {
    __shared__ float s_uh[LL][ZZ], s_w[LL][ZZ], s_b[LL], s_uhw[LL];
    int tid = threadIdx.x;
    if (tid < LL) {
        float w0 = fw[tid * 3], w1 = fw[tid * 3 + 1], w2 = fw[tid * 3 + 2];
        float u0 = fu[tid * 3], u1 = fu[tid * 3 + 1], u2 = fu[tid * 3 + 2];
        float wu = w0 * u0 + w1 * u1 + w2 * u2;
        float m = -1.f + softplus_(wu);
        float c = (m - wu) / (w0 * w0 + w1 * w1 + w2 * w2 + 1e-7f);
        float uh0 = u0 + c * w0, uh1 = u1 + c * w1, uh2 = u2 + c * w2;
        s_uh[tid][0] = uh0; s_uh[tid][1] = uh1; s_uh[tid][2] = uh2;
        s_w[tid][0] = w0; s_w[tid][1] = w1; s_w[tid][2] = w2;
        s_b[tid] = fb[tid];
        s_uhw[tid] = uh0 * w0 + uh1 * w1 + uh2 * w2;
    }
    __syncthreads();
    int idx = blockIdx.x * blockDim.x + tid;
    if (idx >= BT) return;
    float z0 = zgen[idx * 3], z1 = zgen[idx * 3 + 1], z2 = zgen[idx * 3 + 2];
    float ld = 0.f;
    #pragma unroll
    for (int l = 0; l < LL; l++) {
        float lin = z0 * s_w[l][0] + z1 * s_w[l][1] + z2 * s_w[l][2] + s_b[l];
        float t = tanhf(lin);
        z0 += s_uh[l][0] * t; z1 += s_uh[l][1] * t; z2 += s_uh[l][2] * t;
        float det = 1.f + (1.f - t * t) * s_uhw[l];
        ld += logf(fabsf(det) + 1e-7f);
    }
    zfin[idx * 3] = z0; zfin[idx * 3 + 1] = z1; zfin[idx * 3 + 2] = z2;
    ldj[idx] = ld;
}

// ---------------- launch ----------------
extern "C" void kernel_launch(void* const* d_in, const int* in_sizes, int n_in,
                              void* d_out, int out_size) {
    const float* x       = (const float*)d_in[0];
    const float* eps     = (const float*)d_in[1];
    const float* enc_Wih = (const float*)d_in[2];
    const float* enc_Whh = (const float*)d_in[3];
    const float* enc_bih = (const float*)d_in[4];
    const float* enc_bhh = (const float*)d_in[5];
    const float* enc_W1  = (const float*)d_in[6];
    const float* enc_b1  = (const float*)d_in[7];
    const float* enc_W2  = (const float*)d_in[8];
    const float* enc_b2  = (const float*)d_in[9];
    const float* zm_W    = (const float*)d_in[10];
    const float* zm_b    = (const float*)d_in[11];
    const float* zs_W    = (const float*)d_in[12];
    const float* zs_b    = (const float*)d_in[13];
    const float* flow_w  = (const float*)d_in[14];
    const float* flow_b  = (const float*)d_in[15];
    const float* flow_u  = (const float*)d_in[16];
    const float* dec_Wih = (const float*)d_in[17];
    const float* dec_Whh = (const float*)d_in[18];
    const float* dec_bih = (const float*)d_in[19];
    const float* dec_bhh = (const float*)d_in[20];
    const float* dec_W1  = (const float*)d_in[21];
    const float* dec_b1  = (const float*)d_in[22];
    const float* dec_W2  = (const float*)d_in[23];
    const float* dec_b2  = (const float*)d_in[24];
    const float* xm_W    = (const float*)d_in[25];
    const float* xm_b    = (const float*)d_in[26];
    const float* xs_W    = (const float*)d_in[27];
    const float* xs_b    = (const float*)d_in[28];

    float *gi, *seq1, *seq2, *wtf;
    cudaGetSymbolAddress((void**)&gi, g_gi);
    cudaGetSymbolAddress((void**)&seq1, g_seq1);
    cudaGetSymbolAddress((void**)&seq2, g_seq2);
    cudaGetSymbolAddress((void**)&wtf, g_wtf);
    float* wW1e = wtf + 0;
    float* wW2e = wtf + 250000;
    float* wW1d = wtf + 500000;
    float* wW2d = wtf + 750000;
    float* wXm  = wtf + 1000000;
    float* wXs  = wtf + 1019000;

    float* out  = (float*)d_out;
    float* o_mu = out;
    float* o_sd = o_mu + (size_t)BT * XX;
    float* o_zg = o_sd + (size_t)BT * XX;
    float* o_zf = o_zg + (size_t)BT * ZZ;
    float* o_zm = o_zf + (size_t)BT * ZZ;
    float* o_zs = o_zm + (size_t)BT * ZZ;
    float* o_ld = o_zs + (size_t)BT * ZZ;

    const int GRUSM = GRU_FLOATS * 4;      // 206,016 B
    const int GEMSM = 4 * ABUF * 4;        // 73,728 B
    static bool attr_done = false;
    if (!attr_done) {
        cudaFuncSetAttribute(k_gru_tc<0>, cudaFuncAttributeMaxDynamicSharedMemorySize, GRUSM);
        cudaFuncSetAttribute(k_gru_tc<1>, cudaFuncAttributeMaxDynamicSharedMemorySize, GRUSM);
        cudaFuncSetAttribute((const void*)gemm_tc2<0,0>, cudaFuncAttributeMaxDynamicSharedMemorySize, GEMSM);
        cudaFuncSetAttribute((const void*)gemm_tc2<1,1>, cudaFuncAttributeMaxDynamicSharedMemorySize, GEMSM);
        cudaFuncSetAttribute((const void*)gemm_tc2<2,0>, cudaFuncAttributeMaxDynamicSharedMemorySize, GEMSM);
        attr_done = true;
    }

    // ---- pre-convert K=500 weights to tf32 ----
    k_cvt<<<(250000 + 255) / 256, 256>>>(enc_W1, wW1e, 250000);
    k_cvt<<<(250000 + 255) / 256, 256>>>(enc_W2, wW2e, 250000);
    k_cvt<<<(250000 + 255) / 256, 256>>>(dec_W1, wW1d, 250000);
    k_cvt<<<(250000 + 255) / 256, 256>>>(dec_W2, wW2d, 250000);
    k_cvt<<<(19000 + 255) / 256, 256>>>(xm_W, wXm, 19000);
    k_cvt<<<(19000 + 255) / 256, 256>>>(xs_W, wXs, 19000);

    const dim3 gGi((G3 + 127) / 128, (BT + 127) / 128);    // 12 x 400
    const dim3 gPost((HH + 127) / 128, (BT + 127) / 128);  // 4 x 400
    const dim3 gProj(1, BT / 128);                         // 1 x 400

    // ---- Encoder ----
    gemm_tc<0><<<gGi, 256>>>(x, enc_Wih, enc_bih, gi, BT, G3, XX);
    k_gru_tc<0><<<NBLK, 256, GRUSM>>>(gi, nullptr, nullptr, enc_Whh, enc_bhh, seq1);
    gemm_tc2<1,1><<<gPost, 256, GEMSM>>>(seq1, wW1e, enc_b1, seq2, BT, HH, HH);
    gemm_tc2<1,1><<<gPost, 256, GEMSM>>>(seq2, wW2e, enc_b2, seq1, BT, HH, HH);

    // ---- Latent scan + flows ----
    k_latent<<<BB, 192>>>(seq1, eps, zm_W, zm_b, zs_W, zs_b, o_zg, o_zm, o_zs);
    k_flow<<<(BT + 255) / 256, 256>>>(o_zg, flow_w, flow_b, flow_u, o_zf, o_ld);

    // ---- Decoder ----
    k_gru_tc<1><<<NBLK, 256, GRUSM>>>(o_zf, dec_Wih, dec_bih, dec_Whh, dec_bhh, seq2);
    gemm_tc2<1,1><<<gPost, 256, GEMSM>>>(seq2, wW1d, dec_b1, seq1, BT, HH, HH);
    gemm_tc2<1,1><<<gPost, 256, GEMSM>>>(seq1, wW2d, dec_b2, seq2, BT, HH, HH);

    // ---- Output projections ----
    gemm_tc2<0,0><<<gProj, 256, GEMSM>>>(seq2, wXm, xm_b, o_mu, BT, XX, HH);
    gemm_tc2<2,0><<<gProj, 256, GEMSM>>>(seq2, wXs, xs_b, o_sd, BT, XX, HH);
}

// round 14
// speedup vs baseline: 8.7032x; 1.0819x over previous
#include <cuda_runtime.h>
#include <math.h>

// ---------------- problem dims ----------------
#define BB  512
#define TT  100
#define XX  38
#define ZZ  3
#define HH  500
#define LL  20
#define G3  (3*HH)      // 1500
#define BT  (BB*TT)     // 51200

// ---- persistent GRU tiling ----
#define NBLK   128      // 4 m-groups x 32 j-tiles
#define MTILE  128
#define JTILE  16
#define CTILE  48       // 3 gates * JTILE
#define WPITCH 516      // Ws k-pitch (mod 32 = 4 -> conflict-free)
#define AP2    68       // GRU A pitch (mod 32 = 4)
#define GCH    64       // GRU k-chunk
#define ABUF2  (128*AP2)   // 8704 floats per buffer
#define CPITCH 52
// smem float offsets (Cs aliased onto As: used only after MMA loop)
#define OFF_WS  0
#define OFF_AS  (OFF_WS + CTILE*WPITCH)        // 24768
#define OFF_HS  (OFF_AS + 3*ABUF2)             // 50880
#define OFF_ZT  (OFF_HS + 128*JTILE)           // 52928
#define OFF_WI  (OFF_ZT + 384)                 // 53312
#define OFF_BI  (OFF_WI + CTILE*3)             // 53456
#define OFF_BH  (OFF_BI + CTILE)               // 53504
#define GRU_FLOATS (OFF_BH + CTILE)            // 53552 -> 214,208 B

// ---- pipelined GEMM tiling ----
#define GPITCH 36
#define ABUF   (128*GPITCH)

// ---------------- scratch ----------------
__device__ float g_gi[(size_t)BT * G3];
__device__ float g_seq1[(size_t)BT * HH];
__device__ float g_seq2[(size_t)BT * HH];
__device__ float g_wtf[1000000];
__device__ unsigned g_cnt4[128];    // per-m-group barrier counters (stride 32)
__device__ unsigned g_sense4[128];

// ---------------- helpers ----------------
__device__ __forceinline__ float sigm_(float x) { return 1.f / (1.f + expf(-x)); }
__device__ __forceinline__ float softplus_(float x) { return x > 15.f ? x : log1pf(expf(x)); }
__device__ __forceinline__ float f2tf(float f) {
    unsigned u; asm("cvt.rna.tf32.f32 %0, %1;" : "=r"(u) : "f"(f));
    return __uint_as_float(u);
}
__device__ __forceinline__ unsigned tfbits(float f) {
    unsigned u; asm("cvt.rna.tf32.f32 %0, %1;" : "=r"(u) : "f"(f));
    return u;
}
__device__ __forceinline__ void mma_tf32(float* c, const unsigned* a, const unsigned* b) {
    asm volatile("mma.sync.aligned.m16n8k8.row.col.f32.tf32.tf32.f32 "
        "{%0,%1,%2,%3}, {%4,%5,%6,%7}, {%8,%9}, {%0,%1,%2,%3};\n"
        : "+f"(c[0]), "+f"(c[1]), "+f"(c[2]), "+f"(c[3])
        : "r"(a[0]), "r"(a[1]), "r"(a[2]), "r"(a[3]), "r"(b[0]), "r"(b[1]));
}
__device__ __forceinline__ unsigned smaddr(const void* p) {
    return (unsigned)__cvta_generic_to_shared(p);
}
__device__ __forceinline__ void cpasync16(unsigned dst, const void* src, int bytes) {
    asm volatile("cp.async.cg.shared.global [%0], [%1], 16, %2;"
                 :: "r"(dst), "l"(src), "r"(bytes));
}
__device__ __forceinline__ void cpcommit() { asm volatile("cp.async.commit_group;"); }
__device__ __forceinline__ void cpwait0()  { asm volatile("cp.async.wait_group 0;"); }
__device__ __forceinline__ void cpwait1()  { asm volatile("cp.async.wait_group 1;"); }

// ---------------- per-m-group barrier (32 CTAs each) ----------------
__device__ __forceinline__ void gsync_mt(int mt, unsigned gen, unsigned base) {
    __syncthreads();
    if (threadIdx.x == 0) {
        __threadfence();
        unsigned a = atomicAdd(&g_cnt4[mt * 32], 1);
        if (a == 31) {
            g_cnt4[mt * 32] = 0;
            __threadfence();
            *(volatile unsigned*)&g_sense4[mt * 32] = base + gen;
        } else {
            while ((unsigned)(*(volatile unsigned*)&g_sense4[mt * 32] - base) < gen) {}
        }
        __threadfence();
    }
    __syncthreads();
}

// ---------------- tf32 cvt fill ----------------
__global__ void k_cvt(const float* __restrict__ s, float* __restrict__ d, int n) {
    int i = blockIdx.x * blockDim.x + threadIdx.x;
    if (i < n) d[i] = f2tf(s[i]);
}

// ---------------- persistent GRU ----------------
// DEC=0: giz = input gates [B,T,3H] (incl bih). DEC=1: giz = z_fin [B,T,3].
template<int DEC>
__global__ void __launch_bounds__(256, 1)
k_gru_tc(const float* __restrict__ giz,
         const float* __restrict__ Wih, const float* __restrict__ bih,
         const float* __restrict__ Whh, const float* __restrict__ bhh,
         float* __restrict__ seq) {
    extern __shared__ float sm[];
    float* Ws  = sm + OFF_WS;
    float* As  = sm + OFF_AS;
    float* Cs  = sm + OFF_AS;      // aliased: valid only after MMA loop completes
    float* Hs  = sm + OFF_HS;
    float* Zt  = sm + OFF_ZT;
    float* Wis = sm + OFF_WI;
    float* bis = sm + OFF_BI;
    float* bhs = sm + OFF_BH;

    const int blk = blockIdx.x;
    const int mt = blk >> 5, jt = blk & 31;
    const int bm = mt * MTILE;
    const int jbase = jt * JTILE;
    const int tid = threadIdx.x;
    const int warp = tid >> 5, lane = tid & 31;
    const int wm = warp >> 1, wn = warp & 1;   // warp tile m32 x n24
    const int gq = lane >> 2, lt = lane & 3;
    const unsigned as_u = smaddr(As);

    // ---- init: Whh slice (tf32), biases, dec Wih tile, zero Hs ----
    for (int i = tid; i < CTILE * 512; i += 256) {
        int c = i >> 9, k = i & 511;
        int gate = c >> 4, jj = c & 15;
        int j = jbase + jj;
        float v = 0.f;
        if (j < HH && k < HH) v = f2tf(Whh[(size_t)(gate * HH + j) * HH + k]);
        Ws[c * WPITCH + k] = v;
    }
    for (int i = tid; i < 128 * JTILE; i += 256) Hs[i] = 0.f;
    if (tid < CTILE) {
        int gate = tid >> 4, jj = tid & 15;
        int j = jbase + jj;
        int row = gate * HH + ((j < HH) ? j : 0);
        bhs[tid] = bhh[row];
        if (DEC) {
            bis[tid] = bih[row];
            Wis[tid * 3 + 0] = Wih[3 * row + 0];
            Wis[tid * 3 + 1] = Wih[3 * row + 1];
            Wis[tid * 3 + 2] = Wih[3 * row + 2];
        }
    }
    __syncthreads();

    unsigned base = *(volatile unsigned*)&g_sense4[mt * 32];

    for (int t = 0; t < TT; t++) {
        float acc[2][3][4] = {};
        if (t > 0) {
            auto docopy = [&](int c, int buf) {
                int kbase = c * GCH;
                #pragma unroll
                for (int i = 0; i < 8; i++) {
                    int idx = tid + i * 256;
                    int row = idx >> 4, ch = idx & 15;
                    int gk = kbase + ch * 4;
                    int gks = (gk < 496) ? gk : 496;
                    const float* src = seq + ((size_t)(bm + row) * TT + (t - 1)) * HH + gks;
                    unsigned dst = as_u + (unsigned)((buf * ABUF2 + row * AP2 + ch * 4) * 4);
                    cpasync16(dst, src, (gk < HH) ? 16 : 0);
                }
                cpcommit();
            };
            docopy(0, 0);
            docopy(1, 1);
            for (int c = 0; c < 8; c++) {
                if (c == 7) cpwait0(); else cpwait1();
                __syncthreads();
                if (c + 2 < 8) docopy(c + 2, (c + 2) % 3);
                const float* Ab = As + (c % 3) * ABUF2;
                #pragma unroll
                for (int ks = 0; ks < GCH; ks += 8) {
                    int kg = c * GCH + ks;
                    unsigned a[2][4], b[3][2];
                    #pragma unroll
                    for (int mi = 0; mi < 2; mi++) {
                        int row = wm * 32 + mi * 16 + gq;
                        a[mi][0] = __float_as_uint(Ab[row * AP2 + ks + lt]);
                        a[mi][1] = __float_as_uint(Ab[(row + 8) * AP2 + ks + lt]);
                        a[mi][2] = __float_as_uint(Ab[row * AP2 + ks + lt + 4]);
                        a[mi][3] = __float_as_uint(Ab[(row + 8) * AP2 + ks + lt + 4]);
                    }
                    #pragma unroll
                    for (int ni = 0; ni < 3; ni++) {
                        int cc = wn * 24 + ni * 8 + gq;
                        b[ni][0] = __float_as_uint(Ws[cc * WPITCH + kg + lt]);
                        b[ni][1] = __float_as_uint(Ws[cc * WPITCH + kg + lt + 4]);
                    }
                    #pragma unroll
                    for (int mi = 0; mi < 2; mi++)
                        #pragma unroll
                        for (int ni = 0; ni < 3; ni++)
                            mma_tf32(acc[mi][ni], a[mi], b[ni]);
                }
            }
            __syncthreads();   // all MMA done; As region now reusable as Cs
        }
        // ---- stash hidden-gate tile into Cs (aliased over As) ----
        #pragma unroll
        for (int mi = 0; mi < 2; mi++)
            #pragma unroll
            for (int ni = 0; ni < 3; ni++) {
                int r0 = wm * 32 + mi * 16 + gq;
                int c0 = wn * 24 + ni * 8 + 2 * lt;
                *(float2*)&Cs[r0 * CPITCH + c0] = make_float2(acc[mi][ni][0], acc[mi][ni][1]);
                *(float2*)&Cs[(r0 + 8) * CPITCH + c0] = make_float2(acc[mi][ni][2], acc[mi][ni][3]);
            }
        if (DEC) {
            for (int i = tid; i < MTILE * ZZ; i += 256)
                Zt[i] = giz[((size_t)(bm + (i / 3)) * TT + t) * ZZ + (i % 3)];
        }
        __syncthreads();
        // ---- gate phase (float4 per thread over 4 consecutive j) ----
        for (int u4 = tid; u4 < MTILE * 4; u4 += 256) {
            int m = u4 >> 2, jq = u4 & 3;
            int jj = jq * 4;
            int j = jbase + jj;
            if (j < HH) {   // HH%4==0 -> full float4 in range
                int b = bm + m;
                float4 cr = *(float4*)&Cs[m * CPITCH + jj];
                float4 cz = *(float4*)&Cs[m * CPITCH + 16 + jj];
                float4 cn = *(float4*)&Cs[m * CPITCH + 32 + jj];
                float4 br = *(float4*)&bhs[jj];
                float4 bz = *(float4*)&bhs[16 + jj];
                float4 bn = *(float4*)&bhs[32 + jj];
                float ghr[4] = {cr.x + br.x, cr.y + br.y, cr.z + br.z, cr.w + br.w};
                float ghz[4] = {cz.x + bz.x, cz.y + bz.y, cz.z + bz.z, cz.w + bz.w};
                float ghn[4] = {cn.x + bn.x, cn.y + bn.y, cn.z + bn.z, cn.w + bn.w};
                float gir[4], gzv[4], gin[4];
                if (DEC) {
                    float z0 = Zt[m * 3], z1 = Zt[m * 3 + 1], z2 = Zt[m * 3 + 2];
                    #pragma unroll
                    for (int q = 0; q < 4; q++) {
                        int jr = jj + q, jz = 16 + jj + q, jn = 32 + jj + q;
                        gir[q] = bis[jr] + Wis[jr*3]*z0 + Wis[jr*3+1]*z1 + Wis[jr*3+2]*z2;
                        gzv[q] = bis[jz] + Wis[jz*3]*z0 + Wis[jz*3+1]*z1 + Wis[jz*3+2]*z2;
                        gin[q] = bis[jn] + Wis[jn*3]*z0 + Wis[jn*3+1]*z1 + Wis[jn*3+2]*z2;
                    }
                } else {
                    const float* gb = giz + ((size_t)b * TT + t) * G3;
                    float4 a0 = *(const float4*)&gb[j];
                    float4 a1 = *(const float4*)&gb[HH + j];
                    float4 a2 = *(const float4*)&gb[2 * HH + j];
                    gir[0]=a0.x; gir[1]=a0.y; gir[2]=a0.z; gir[3]=a0.w;
                    gzv[0]=a1.x; gzv[1]=a1.y; gzv[2]=a1.z; gzv[3]=a1.w;
                    gin[0]=a2.x; gin[1]=a2.y; gin[2]=a2.z; gin[3]=a2.w;
                }
                float4 hp4 = *(float4*)&Hs[m * 16 + jj];
                float hp[4] = {hp4.x, hp4.y, hp4.z, hp4.w};
                float hn[4];
                #pragma unroll
                for (int q = 0; q < 4; q++) {
                    float r  = sigm_(gir[q] + ghr[q]);
                    float zg = sigm_(gzv[q] + ghz[q]);
                    float n  = tanhf(gin[q] + r * ghn[q]);
                    hn[q] = f2tf((1.f - zg) * n + zg * hp[q]);
                }
                float4 hn4 = make_float4(hn[0], hn[1], hn[2], hn[3]);
                *(float4*)&Hs[m * 16 + jj] = hn4;
                *(float4*)&seq[((size_t)b * TT + t) * HH + j] = hn4;
            }
        }
        gsync_mt(mt, t + 1, base);
    }
}

// ---------------- pipelined tf32 GEMM: C = act(A @ W^T + bias) ----------------
// A pre-tf32-rounded; W pre-rounded unless CVTB=1 (cvt in register). M%128==0, K%4==0.
template<int ACT, int TFOUT, int CVTB>
__global__ void __launch_bounds__(256, 2)
gemm_tc2(const float* __restrict__ A, const float* __restrict__ W,
         const float* __restrict__ bias, float* __restrict__ C,
         int M, int N, int K) {
    extern __shared__ float dsm[];
    float* As = dsm;
    float* Bs = dsm + 2 * ABUF;
    const int bn = blockIdx.x * 128, bm = blockIdx.y * 128;
    const int tid = threadIdx.x;
    const int warp = tid >> 5, lane = tid & 31;
    const int wm = warp >> 2, wn = warp & 3;
    const int gq = lane >> 2, lt = lane & 3;
    const unsigned as_u = smaddr(As), bs_u = smaddr(Bs);
    const int nt = (K + 31) / 32;

    auto docopy = [&](int c, int buf) {
        int kbase = c * 32;
        #pragma unroll
        for (int i = 0; i < 4; i++) {
            int idx = tid + i * 256;
            int row = idx >> 3, ch = idx & 7;
            int gk = kbase + ch * 4;
            int gks = (gk < K) ? gk : 0;
            unsigned off = (unsigned)((buf * ABUF + row * GPITCH + ch * 4) * 4);
            cpasync16(as_u + off, A + (size_t)(bm + row) * K + gks, (gk < K) ? 16 : 0);
            int gn = bn + row;
            cpasync16(bs_u + off, W + (size_t)((gn < N) ? gn : 0) * K + gks, (gn < N && gk < K) ? 16 : 0);
        }
        cpcommit();
    };

    float acc[4][4][4] = {};
    docopy(0, 0);
    for (int c = 0; c < nt; c++) {
        cpwait0();
        __syncthreads();
        if (c + 1 < nt) docopy(c + 1, (c + 1) & 1);
        const float* Ab = As + (c & 1) * ABUF;
        const float* Bb = Bs + (c & 1) * ABUF;
        #pragma unroll
        for (int ks = 0; ks < 32; ks += 8) {
            unsigned a[4][4], b[4][2];
            #pragma unroll
            for (int mi = 0; mi < 4; mi++) {
                int row = wm * 64 + mi * 16 + gq;
                a[mi][0] = __float_as_uint(Ab[row * GPITCH + ks + lt]);
                a[mi][1] = __float_as_uint(Ab[(row + 8) * GPITCH + ks + lt]);
                a[mi][2] = __float_as_uint(Ab[row * GPITCH + ks + lt + 4]);
                a[mi][3] = __float_as_uint(Ab[(row + 8) * GPITCH + ks + lt + 4]);
            }
            #pragma unroll
            for (int ni = 0; ni < 4; ni++) {
                int nl = wn * 32 + ni * 8 + gq;
                if (CVTB) {
                    b[ni][0] = tfbits(Bb[nl * GPITCH + ks + lt]);
                    b[ni][1] = tfbits(Bb[nl * GPITCH + ks + lt + 4]);
                } else {
                    b[ni][0] = __float_as_uint(Bb[nl * GPITCH + ks + lt]);
                    b[ni][1] = __float_as_uint(Bb[nl * GPITCH + ks + lt + 4]);
                }
            }
            #pragma unroll
            for (int mi = 0; mi < 4; mi++)
                #pragma unroll
                for (int ni = 0; ni < 4; ni++)
                    mma_tf32(acc[mi][ni], a[mi], b[ni]);
        }
    }
    #pragma unroll
    for (int mi = 0; mi < 4; mi++) {
        #pragma unroll
        for (int ni = 0; ni < 4; ni++) {
            int gn = bn + wn * 32 + ni * 8 + 2 * lt;
            if (gn >= N) continue;
            #pragma unroll
            for (int half = 0; half < 2; half++) {
                int gm = bm + wm * 64 + mi * 16 + gq + half * 8;
                float v0 = acc[mi][ni][half * 2 + 0] + bias[gn];
                float v1 = acc[mi][ni][half * 2 + 1] + bias[gn + 1];
                if (ACT == 1) { v0 = v0 > 0.f ? v0 : 0.1f * v0; v1 = v1 > 0.f ? v1 : 0.1f * v1; }
                else if (ACT == 2) { v0 = softplus_(v0) + 1e-4f; v1 = softplus_(v1) + 1e-4f; }
                if (TFOUT) { v0 = f2tf(v0); v1 = f2tf(v1); }
                *(float2*)&C[(size_t)gm * N + gn] = make_float2(v0, v1);
            }
        }
    }
}

// ---------------- generic tf32 GEMM (K=38 gi path) ----------------
#define APITCH 136
template<int ACT>
__global__ void __launch_bounds__(256, 1)
gemm_tc(const float* __restrict__ A, const float* __restrict__ W,
        const float* __restrict__ bias, float* __restrict__ C,
        int M, int N, int K) {
    __shared__ float As[16 * APITCH];
    __shared__ float Bs[128 * 20];
    const int bn = blockIdx.x * 128, bm = blockIdx.y * 128;
    const int tid = threadIdx.x;
    const int warp = tid >> 5, lane = tid & 31;
    const int wm = warp >> 2, wn = warp & 3;
    const int gq = lane >> 2, lt = lane & 3;
    const int r_ = tid >> 1, kq_ = (tid & 1) * 8;

    float acc[4][4][4] = {};
    for (int kbase = 0; kbase < K; kbase += 16) {
        {
            int gm = bm + r_;
            const float* ap = A + (size_t)gm * K + kbase + kq_;
            #pragma unroll
            for (int q = 0; q < 2; q++) {
                int gk = kbase + kq_ + q * 4;
                float4 v = make_float4(0.f, 0.f, 0.f, 0.f);
                if (gm < M) {
                    if (gk + 0 < K) v.x = ap[q * 4 + 0];
                    if (gk + 1 < K) v.y = ap[q * 4 + 1];
                    if (gk + 2 < K) v.z = ap[q * 4 + 2];
                    if (gk + 3 < K) v.w = ap[q * 4 + 3];
                }
                int kk = kq_ + q * 4;
                As[(kk + 0) * APITCH + r_] = f2tf(v.x);
                As[(kk + 1) * APITCH + r_] = f2tf(v.y);
                As[(kk + 2) * APITCH + r_] = f2tf(v.z);
                As[(kk + 3) * APITCH + r_] = f2tf(v.w);
            }
        }
        {
            int gn = bn + r_;
            const float* wp = W + (size_t)gn * K + kbase + kq_;
            #pragma unroll
            for (int q = 0; q < 2; q++) {
                int gk = kbase + kq_ + q * 4;
                float4 v = make_float4(0.f, 0.f, 0.f, 0.f);
                if (gn < N) {
                    if (gk + 0 < K) v.x = wp[q * 4 + 0];
                    if (gk + 1 < K) v.y = wp[q * 4 + 1];
                    if (gk + 2 < K) v.z = wp[q * 4 + 2];
                    if (gk + 3 < K) v.w = wp[q * 4 + 3];
                }
                int kk = kq_ + q * 4;
                Bs[r_ * 20 + kk + 0] = f2tf(v.x);
                Bs[r_ * 20 + kk + 1] = f2tf(v.y);
                Bs[r_ * 20 + kk + 2] = f2tf(v.z);
                Bs[r_ * 20 + kk + 3] = f2tf(v.w);
            }
        }
        __syncthreads();
        #pragma unroll
        for (int ks = 0; ks < 16; ks += 8) {
            unsigned a[4][4], b[4][2];
            #pragma unroll
            for (int mi = 0; mi < 4; mi++) {
                int row = wm * 64 + mi * 16 + gq;
                a[mi][0] = __float_as_uint(As[(ks + lt) * APITCH + row]);
                a[mi][1] = __float_as_uint(As[(ks + lt) * APITCH + row + 8]);
                a[mi][2] = __float_as_uint(As[(ks + lt + 4) * APITCH + row]);
                a[mi][3] = __float_as_uint(As[(ks + lt + 4) * APITCH + row + 8]);
            }
            #pragma unroll
            for (int ni = 0; ni < 4; ni++) {
                int nl = wn * 32 + ni * 8 + gq;
                b[ni][0] = __float_as_uint(Bs[nl * 20 + ks + lt]);
                b[ni][1] = __float_as_uint(Bs[nl * 20 + ks + lt + 4]);
            }
            #pragma unroll
            for (int mi = 0; mi < 4; mi++)
                #pragma unroll
                for (int ni = 0; ni < 4; ni++)
                    mma_tf32(acc[mi][ni], a[mi], b[ni]);
        }
        __syncthreads();
    }
    #pragma unroll
    for (int mi = 0; mi < 4; mi++) {
        #pragma unroll
        for (int ni = 0; ni < 4; ni++) {
            int gn = bn + wn * 32 + ni * 8 + 2 * lt;
            if (gn >= N) continue;
            #pragma unroll
            for (int half = 0; half < 2; half++) {
                int gm = bm + wm * 64 + mi * 16 + gq + half * 8;
                if (gm >= M) continue;
                float v0 = acc[mi][ni][half * 2 + 0] + bias[gn];
                float v1 = acc[mi][ni][half * 2 + 1] + bias[gn + 1];
                if (ACT == 1) { v0 = v0 > 0.f ? v0 : 0.1f * v0; v1 = v1 > 0.f ? v1 : 0.1f * v1; }
                else if (ACT == 2) { v0 = softplus_(v0) + 1e-4f; v1 = softplus_(v1) + 1e-4f; }
                *(float2*)&C[(size_t)gm * N + gn] = make_float2(v0, v1);
            }
        }
    }
}

// ---------------- latent scan ----------------
__global__ void k_latent(const float* __restrict__ hpost, const float* __restrict__ eps,
                         const float* __restrict__ zmW, const float* __restrict__ zmb,
                         const float* __restrict__ zsW, const float* __restrict__ zsb,
                         float* __restrict__ zg, float* __restrict__ zm, float* __restrict__ zs) {
    int b = blockIdx.x;
    __shared__ float red[6];
    __shared__ float zprev[ZZ];
    int tid = threadIdx.x;
    int w = tid >> 5, lane = tid & 31;
    if (tid < ZZ) zprev[tid] = 0.f;
    __syncthreads();
    const float* Wrow = (w < 3) ? (zmW + (size_t)w * (HH + ZZ)) : (zsW + (size_t)(w - 3) * (HH + ZZ));
    for (int t = 0; t < TT; t++) {
        const float* hrow = hpost + ((size_t)b * TT + t) * HH;
        float s = 0.f;
        for (int k = lane; k < HH; k += 32) s += hrow[k] * Wrow[k];
        if (lane < ZZ) s += zprev[lane] * Wrow[HH + lane];
        #pragma unroll
        for (int o = 16; o; o >>= 1) s += __shfl_down_sync(0xffffffffu, s, o);
        if (lane == 0) red[w] = s;
        __syncthreads();
        if (tid < ZZ) {
            float mu = red[tid] + zmb[tid];
            float sd = softplus_(red[3 + tid] + zsb[tid]) + 1e-4f;
            size_t o = ((size_t)b * TT + t) * ZZ + tid;
            float zt = mu + sd * eps[o];
            zg[o] = zt; zm[o] = mu; zs[o] = sd;
            zprev[tid] = zt;
        }
        __syncthreads();
    }
}

// ---------------- planar flow stack ----------------
__global__ void k_flow(const float* __restrict__ zgen,
                       const float* __restrict__ fw, const float* __restrict__ fb,
                       const float* __restrict__ fu,
                       float* __restrict__ zfin, float* __restrict__ ldj) {
    __shared__ float s_uh[LL][ZZ], s_w[LL][ZZ], s_b[LL], s_uhw[LL];
    int tid = threadIdx.x;
    if (tid < LL) {
        float w0 = fw[tid * 3], w1 = fw[tid * 3 + 1], w2 = fw[tid * 3 + 2];
        float u0 = fu[tid * 3], u1 = fu[tid * 3 + 1], u2 = fu[tid * 3 + 2];
        float wu = w0 * u0 + w1 * u1 + w2 * u2;
        float m = -1.f + softplus_(wu);
        float c = (m - wu) / (w0 * w0 + w1 * w1 + w2 * w2 + 1e-7f);
        float uh0 = u0 + c * w0, uh1 = u1 + c * w1, uh2 = u2 + c * w2;
        s_uh[tid][0] = uh0; s_uh[tid][1] = uh1; s_uh[tid][2] = uh2;
        s_w[tid][0] = w0; s_w[tid][1] = w1; s_w[tid][2] = w2;
        s_b[tid] = fb[tid];
        s_uhw[tid] = uh0 * w0 + uh1 * w1 + uh2 * w2;
    }
    __syncthreads();
    int idx = blockIdx.x * blockDim.x + tid;
    if (idx >= BT) return;
    float z0 = zgen[idx * 3], z1 = zgen[idx * 3 + 1], z2 = zgen[idx * 3 + 2];
    float ld = 0.f;
    #pragma unroll
    for (int l = 0; l < LL; l++) {
        float lin = z0 * s_w[l][0] + z1 * s_w[l][1] + z2 * s_w[l][2] + s_b[l];
        float t = tanhf(lin);
        z0 += s_uh[l][0] * t; z1 += s_uh[l][1] * t; z2 += s_uh[l][2] * t;
        float det = 1.f + (1.f - t * t) * s_uhw[l];
        ld += logf(fabsf(det) + 1e-7f);
    }
    zfin[idx * 3] = z0; zfin[idx * 3 + 1] = z1; zfin[idx * 3 + 2] = z2;
    ldj[idx] = ld;
}

// ---------------- launch ----------------
extern "C" void kernel_launch(void* const* d_in, const int* in_sizes, int n_in,
                              void* d_out, int out_size) {
    const float* x       = (const float*)d_in[0];
    const float* eps     = (const float*)d_in[1];
    const float* enc_Wih = (const float*)d_in[2];
    const float* enc_Whh = (const float*)d_in[3];
    const float* enc_bih = (const float*)d_in[4];
    const float* enc_bhh = (const float*)d_in[5];
    const float* enc_W1  = (const float*)d_in[6];
    const float* enc_b1  = (const float*)d_in[7];
    const float* enc_W2  = (const float*)d_in[8];
    const float* enc_b2  = (const float*)d_in[9];
    const float* zm_W    = (const float*)d_in[10];
    const float* zm_b    = (const float*)d_in[11];
    const float* zs_W    = (const float*)d_in[12];
    const float* zs_b    = (const float*)d_in[13];
    const float* flow_w  = (const float*)d_in[14];
    const float* flow_b  = (const float*)d_in[15];
    const float* flow_u  = (const float*)d_in[16];
    const float* dec_Wih = (const float*)d_in[17];
    const float* dec_Whh = (const float*)d_in[18];
    const float* dec_bih = (const float*)d_in[19];
    const float* dec_bhh = (const float*)d_in[20];
    const float* dec_W1  = (const float*)d_in[21];
    const float* dec_b1  = (const float*)d_in[22];
    const float* dec_W2  = (const float*)d_in[23];
    const float* dec_b2  = (const float*)d_in[24];
    const float* xm_W    = (const float*)d_in[25];
    const float* xm_b    = (const float*)d_in[26];
    const float* xs_W    = (const float*)d_in[27];
    const float* xs_b    = (const float*)d_in[28];

    float *gi, *seq1, *seq2, *wtf;
    cudaGetSymbolAddress((void**)&gi, g_gi);
    cudaGetSymbolAddress((void**)&seq1, g_seq1);
    cudaGetSymbolAddress((void**)&seq2, g_seq2);
    cudaGetSymbolAddress((void**)&wtf, g_wtf);
    float* wW1e = wtf + 0;
    float* wW2e = wtf + 250000;
    float* wW1d = wtf + 500000;
    float* wW2d = wtf + 750000;

    float* out  = (float*)d_out;
    float* o_mu = out;
    float* o_sd = o_mu + (size_t)BT * XX;
    float* o_zg = o_sd + (size_t)BT * XX;
    float* o_zf = o_zg + (size_t)BT * ZZ;
    float* o_zm = o_zf + (size_t)BT * ZZ;
    float* o_zs = o_zm + (size_t)BT * ZZ;
    float* o_ld = o_zs + (size_t)BT * ZZ;

    const int GRUSM = GRU_FLOATS * 4;      // 214,208 B
    const int GEMSM = 4 * ABUF * 4;        // 73,728 B
    static bool attr_done = false;
    if (!attr_done) {
        cudaFuncSetAttribute(k_gru_tc<0>, cudaFuncAttributeMaxDynamicSharedMemorySize, GRUSM);
        cudaFuncSetAttribute(k_gru_tc<1>, cudaFuncAttributeMaxDynamicSharedMemorySize, GRUSM);
        cudaFuncSetAttribute((const void*)gemm_tc2<0,0,1>, cudaFuncAttributeMaxDynamicSharedMemorySize, GEMSM);
        cudaFuncSetAttribute((const void*)gemm_tc2<1,1,0>, cudaFuncAttributeMaxDynamicSharedMemorySize, GEMSM);
        cudaFuncSetAttribute((const void*)gemm_tc2<2,0,1>, cudaFuncAttributeMaxDynamicSharedMemorySize, GEMSM);
        attr_done = true;
    }

    const dim3 gGi((G3 + 127) / 128, (BT + 127) / 128);    // 12 x 400
    const dim3 gPost((HH + 127) / 128, (BT + 127) / 128);  // 4 x 400
    const dim3 gProj(1, BT / 128);                         // 1 x 400

    // launches 0-3: weight pre-cvt; 4: gi; 5: encoder GRU (ncu -s 5 profiles this)
    k_cvt<<<(250000 + 255) / 256, 256>>>(enc_W1, wW1e, 250000);   // 0
    k_cvt<<<(250000 + 255) / 256, 256>>>(enc_W2, wW2e, 250000);   // 1
    k_cvt<<<(250000 + 255) / 256, 256>>>(dec_W1, wW1d, 250000);   // 2
    k_cvt<<<(250000 + 255) / 256, 256>>>(dec_W2, wW2d, 250000);   // 3
    gemm_tc<0><<<gGi, 256>>>(x, enc_Wih, enc_bih, gi, BT, G3, XX);            // 4
    k_gru_tc<0><<<NBLK, 256, GRUSM>>>(gi, nullptr, nullptr, enc_Whh, enc_bhh, seq1);  // 5
    gemm_tc2<1,1,0><<<gPost, 256, GEMSM>>>(seq1, wW1e, enc_b1, seq2, BT, HH, HH);
    gemm_tc2<1,1,0><<<gPost, 256, GEMSM>>>(seq2, wW2e, enc_b2, seq1, BT, HH, HH);

    k_latent<<<BB, 192>>>(seq1, eps, zm_W, zm_b, zs_W, zs_b, o_zg, o_zm, o_zs);
    k_flow<<<(BT + 255) / 256, 256>>>(o_zg, flow_w, flow_b, flow_u, o_zf, o_ld);

    k_gru_tc<1><<<NBLK, 256, GRUSM>>>(o_zf, dec_Wih, dec_bih, dec_Whh, dec_bhh, seq2);
    gemm_tc2<1,1,0><<<gPost, 256, GEMSM>>>(seq2, wW1d, dec_b1, seq1, BT, HH, HH);
    gemm_tc2<1,1,0><<<gPost, 256, GEMSM>>>(seq1, wW2d, dec_b2, seq2, BT, HH, HH);

    gemm_tc2<0,0,1><<<gProj, 256, GEMSM>>>(seq2, xm_W, xm_b, o_mu, BT, XX, HH);
    gemm_tc2<2,0,1><<<gProj, 256, GEMSM>>>(seq2, xs_W, xs_b, o_sd, BT, XX, HH);
}